// round 3
// baseline (speedup 1.0000x reference)
#include <cuda_runtime.h>
#include <math.h>

// ---------------- problem constants ----------------
#define Ln   2
#define Hn   2048
#define NHn  16
#define NKVn 2
#define HDn  128
#define Sn   1024
#define Pn   1024
#define FFn  5632
#define Tn   (Pn + Sn)       // 2048
#define Gn   (NHn / NKVn)    // 8
#define EPSn 1e-6f
#define SCALEn 0.08838834764831845f  // 1/sqrt(128)

// ---------------- device scratch (static, no allocation) ----------------
static __device__ float g_hid  [Sn * Hn];
static __device__ float g_hnorm[Sn * Hn];
static __device__ float g_q    [Sn * Hn];
static __device__ float g_kbuf [Sn * NKVn * HDn];
static __device__ float g_vbuf [Sn * NKVn * HDn];
static __device__ float g_scores[(size_t)NHn * Sn * Tn];   // 134 MB
static __device__ float g_attn [Sn * Hn];
static __device__ float g_gate [(size_t)Sn * FFn];
static __device__ float g_up   [(size_t)Sn * FFn];

// ---------------- reductions ----------------
__device__ __forceinline__ float warpSum(float v) {
#pragma unroll
    for (int o = 16; o; o >>= 1) v += __shfl_xor_sync(0xffffffffu, v, o);
    return v;
}
__device__ __forceinline__ float warpMax(float v) {
#pragma unroll
    for (int o = 16; o; o >>= 1) v = fmaxf(v, __shfl_xor_sync(0xffffffffu, v, o));
    return v;
}
__device__ float blockSum256(float v) {
    __shared__ float sm[8];
    __shared__ float res;
    v = warpSum(v);
    if ((threadIdx.x & 31) == 0) sm[threadIdx.x >> 5] = v;
    __syncthreads();
    float w = (threadIdx.x < 8) ? sm[threadIdx.x] : 0.f;
    w = warpSum(w);
    if (threadIdx.x == 0) res = w;
    __syncthreads();
    return res;
}
__device__ float blockMax256(float v) {
    __shared__ float sm[8];
    __shared__ float res;
    v = warpMax(v);
    if ((threadIdx.x & 31) == 0) sm[threadIdx.x >> 5] = v;
    __syncthreads();
    float w = (threadIdx.x < 8) ? sm[threadIdx.x] : -1e30f;
    w = warpMax(w);
    if (threadIdx.x == 0) res = w;
    __syncthreads();
    return res;
}

// ---------------- GEMM: C = alpha*A@B(+bias)(+Res), 128x128x16 tiles ----------------
// TB=false: B is [K,N] row-major (ldb over N). TB=true: B is [N,K] row-major (ldb over K).
// Batched over blockIdx.z: A += z*sA, B += (z/bdiv)*sB, C/Res += z*sC.
template<bool TB>
__global__ void __launch_bounds__(256)
gemm_kernel(const float* __restrict__ A, const float* __restrict__ B,
            const float* __restrict__ bias, const float* __restrict__ Res,
            float* __restrict__ C,
            int M, int N, int K, int lda, int ldb, int ldc,
            long long sA, long long sB, long long sC, int bdiv, float alpha)
{
    A += (long long)blockIdx.z * sA;
    B += (long long)(blockIdx.z / bdiv) * sB;
    C += (long long)blockIdx.z * sC;
    const float* R = Res ? Res + (long long)blockIdx.z * sC : (const float*)0;

    __shared__ __align__(16) float As[16][132];
    __shared__ __align__(16) float Bs[16][132];

    const int tid = threadIdx.x;
    const int tx = tid & 15;
    const int ty = tid >> 4;
    const int row0 = blockIdx.y * 128;
    const int col0 = blockIdx.x * 128;

    const int ar = tid >> 2;          // 0..63
    const int ac = (tid & 3) << 2;    // 0,4,8,12
    const int bk = tid >> 4;          // 0..15
    const int bn = (tid & 15) << 2;   // 0..60

    float acc[8][8];
#pragma unroll
    for (int i = 0; i < 8; i++)
#pragma unroll
        for (int j = 0; j < 8; j++) acc[i][j] = 0.f;

    for (int k0 = 0; k0 < K; k0 += 16) {
#pragma unroll
        for (int rr = 0; rr < 2; rr++) {
            int r = ar + rr * 64;
            float4 v = *reinterpret_cast<const float4*>(A + (long long)(row0 + r) * lda + k0 + ac);
            As[ac + 0][r] = v.x; As[ac + 1][r] = v.y;
            As[ac + 2][r] = v.z; As[ac + 3][r] = v.w;
        }
        if (TB) {
#pragma unroll
            for (int rr = 0; rr < 2; rr++) {
                int n = ar + rr * 64;
                float4 v = *reinterpret_cast<const float4*>(B + (long long)(col0 + n) * ldb + k0 + ac);
                Bs[ac + 0][n] = v.x; Bs[ac + 1][n] = v.y;
                Bs[ac + 2][n] = v.z; Bs[ac + 3][n] = v.w;
            }
        } else {
#pragma unroll
            for (int rr = 0; rr < 2; rr++) {
                float4 v = *reinterpret_cast<const float4*>(B + (long long)(k0 + bk) * ldb + col0 + bn + rr * 64);
                *reinterpret_cast<float4*>(&Bs[bk][bn + rr * 64]) = v;
            }
        }
        __syncthreads();
#pragma unroll
        for (int kk = 0; kk < 16; kk++) {
            float a[8], b[8];
            float4 a0 = *reinterpret_cast<const float4*>(&As[kk][ty * 8]);
            float4 a1 = *reinterpret_cast<const float4*>(&As[kk][ty * 8 + 4]);
            float4 b0 = *reinterpret_cast<const float4*>(&Bs[kk][tx * 8]);
            float4 b1 = *reinterpret_cast<const float4*>(&Bs[kk][tx * 8 + 4]);
            a[0]=a0.x; a[1]=a0.y; a[2]=a0.z; a[3]=a0.w;
            a[4]=a1.x; a[5]=a1.y; a[6]=a1.z; a[7]=a1.w;
            b[0]=b0.x; b[1]=b0.y; b[2]=b0.z; b[3]=b0.w;
            b[4]=b1.x; b[5]=b1.y; b[6]=b1.z; b[7]=b1.w;
#pragma unroll
            for (int i = 0; i < 8; i++)
#pragma unroll
                for (int j = 0; j < 8; j++) acc[i][j] += a[i] * b[j];
        }
        __syncthreads();
    }

#pragma unroll
    for (int i = 0; i < 8; i++) {
        long long rbase = (long long)(row0 + ty * 8 + i) * ldc + col0 + tx * 8;
#pragma unroll
        for (int j = 0; j < 8; j += 4) {
            float4 v;
            v.x = acc[i][j + 0] * alpha;
            v.y = acc[i][j + 1] * alpha;
            v.z = acc[i][j + 2] * alpha;
            v.w = acc[i][j + 3] * alpha;
            if (bias) {
                float4 bv = *reinterpret_cast<const float4*>(bias + col0 + tx * 8 + j);
                v.x += bv.x; v.y += bv.y; v.z += bv.z; v.w += bv.w;
            }
            if (R) {
                float4 rv = *reinterpret_cast<const float4*>(R + rbase + j);
                v.x += rv.x; v.y += rv.y; v.z += rv.z; v.w += rv.w;
            }
            *reinterpret_cast<float4*>(C + rbase + j) = v;
        }
    }
}

// ---------------- RMSNorm ----------------
__global__ void __launch_bounds__(256)
rmsnorm_kernel(const float* __restrict__ x, const float* __restrict__ w, float* __restrict__ y)
{
    int s = blockIdx.x;
    const float* row = x + (size_t)s * Hn;
    float4 buf[2];
    float ss = 0.f;
#pragma unroll
    for (int it = 0; it < 2; it++) {
        int j = (it * 256 + threadIdx.x) * 4;
        float4 v = *reinterpret_cast<const float4*>(row + j);
        buf[it] = v;
        ss += v.x * v.x + v.y * v.y + v.z * v.z + v.w * v.w;
    }
    ss = blockSum256(ss);
    float inv = rsqrtf(ss * (1.0f / Hn) + EPSn);
#pragma unroll
    for (int it = 0; it < 2; it++) {
        int j = (it * 256 + threadIdx.x) * 4;
        float4 wv = *reinterpret_cast<const float4*>(w + j);
        float4 o;
        o.x = buf[it].x * inv * wv.x;
        o.y = buf[it].y * inv * wv.y;
        o.z = buf[it].z * inv * wv.z;
        o.w = buf[it].w * inv * wv.w;
        *reinterpret_cast<float4*>(y + (size_t)s * Hn + j) = o;
    }
}

// ---------------- RoPE for Q (in place) ----------------
__global__ void rope_q_kernel(float* __restrict__ q, const int* __restrict__ pos)
{
    int s = blockIdx.x, h = blockIdx.y, d = threadIdx.x; // d in [0,64)
    double ang = (double)pos[s] * exp(-(double)d / 64.0 * 13.815510557964274);
    double sd, cd;
    sincos(ang, &sd, &cd);
    float c = (float)cd, sn = (float)sd;
    float* p = q + ((size_t)s * NHn + h) * HDn;
    float x1 = p[d], x2 = p[d + 64];
    p[d]      = x1 * c - x2 * sn;
    p[d + 64] = x2 * c + x1 * sn;
}

// ---------------- K/V cache assembly (past copy + RoPE'd new K, new V) ----------------
__global__ void kv_cache_kernel(const float* __restrict__ kbuf, const float* __restrict__ vbuf,
                                const float* __restrict__ pastk, const float* __restrict__ pastv,
                                const int* __restrict__ pos,
                                float* __restrict__ kc, float* __restrict__ vc)
{
    int t = blockIdx.x, kv = blockIdx.y, d = threadIdx.x; // d in [0,128)
    size_t oidx = ((size_t)kv * Tn + t) * HDn + d;
    if (t < Pn) {
        size_t pidx = ((size_t)kv * Pn + t) * HDn + d;
        kc[oidx] = pastk[pidx];
        vc[oidx] = pastv[pidx];
    } else {
        int s = t - Pn;
        const float* kr = kbuf + (size_t)s * (NKVn * HDn) + kv * HDn;
        int dr = d & 63;
        double ang = (double)pos[s] * exp(-(double)dr / 64.0 * 13.815510557964274);
        double sd, cd;
        sincos(ang, &sd, &cd);
        float c = (float)cd, sn = (float)sd;
        float val;
        if (d < 64) val = kr[d] * c - kr[d + 64] * sn;
        else        val = kr[d] * c + kr[d - 64] * sn;
        kc[oidx] = val;
        vc[oidx] = vbuf[(size_t)s * (NKVn * HDn) + kv * HDn + d];
    }
}

// ---------------- masked softmax over scores rows (in place) ----------------
__global__ void __launch_bounds__(256)
softmax_kernel(float* __restrict__ scores, const int* __restrict__ pos)
{
    int s = blockIdx.x, h = blockIdx.y;
    float* row = scores + ((size_t)h * Sn + s) * Tn;
    int lim = pos[s];           // valid keys: t <= lim
    int tid = threadIdx.x;
    float v[8];
    float m = -1e30f;
#pragma unroll
    for (int it = 0; it < 2; it++) {
        int t0 = (it * 256 + tid) * 4;
        float4 x = *reinterpret_cast<const float4*>(row + t0);
        float xs[4] = {x.x, x.y, x.z, x.w};
#pragma unroll
        for (int e = 0; e < 4; e++) {
            float val = (t0 + e <= lim) ? xs[e] : -1e30f;
            v[it * 4 + e] = val;
            m = fmaxf(m, val);
        }
    }
    m = blockMax256(m);
    float sum = 0.f;
#pragma unroll
    for (int e = 0; e < 8; e++) {
        float ex = (v[e] > -1e29f) ? expf(v[e] - m) : 0.f;
        v[e] = ex;
        sum += ex;
    }
    sum = blockSum256(sum);
    float inv = 1.f / sum;
#pragma unroll
    for (int it = 0; it < 2; it++) {
        int t0 = (it * 256 + tid) * 4;
        float4 x = make_float4(v[it * 4] * inv, v[it * 4 + 1] * inv,
                               v[it * 4 + 2] * inv, v[it * 4 + 3] * inv);
        *reinterpret_cast<float4*>(row + t0) = x;
    }
}

// ---------------- SiLU(gate) * up -> gate ----------------
__global__ void silu_mul_kernel(float* __restrict__ g, const float* __restrict__ u, int n4)
{
    int i = blockIdx.x * blockDim.x + threadIdx.x;
    if (i < n4) {
        float4 gv = reinterpret_cast<float4*>(g)[i];
        float4 uv = reinterpret_cast<const float4*>(u)[i];
        gv.x = gv.x / (1.f + expf(-gv.x)) * uv.x;
        gv.y = gv.y / (1.f + expf(-gv.y)) * uv.y;
        gv.z = gv.z / (1.f + expf(-gv.z)) * uv.z;
        gv.w = gv.w / (1.f + expf(-gv.w)) * uv.w;
        reinterpret_cast<float4*>(g)[i] = gv;
    }
}

// ---------------- launcher helpers ----------------
template<bool TB>
static void launch_gemm(const float* A, const float* B, const float* bias, const float* Res,
                        float* C, int M, int N, int K, int lda, int ldb, int ldc,
                        long long sA, long long sB, long long sC, int bdiv, float alpha, int batch)
{
    dim3 grid(N / 128, M / 128, batch);
    gemm_kernel<TB><<<grid, 256>>>(A, B, bias, Res, C, M, N, K, lda, ldb, ldc,
                                   sA, sB, sC, bdiv, alpha);
}

extern "C" void kernel_launch(void* const* d_in, const int* in_sizes, int n_in,
                              void* d_out, int out_size)
{
    (void)in_sizes; (void)n_in; (void)out_size;
    const float* embeds = (const float*)d_in[0];
    const int*   pos    = (const int*)  d_in[1];
    const float* past_k = (const float*)d_in[2];
    const float* past_v = (const float*)d_in[3];
    const float* ln1    = (const float*)d_in[4];
    const float* wq     = (const float*)d_in[5];
    const float* bq     = (const float*)d_in[6];
    const float* wk     = (const float*)d_in[7];
    const float* bk     = (const float*)d_in[8];
    const float* wv     = (const float*)d_in[9];
    const float* bv     = (const float*)d_in[10];
    const float* wo     = (const float*)d_in[11];
    const float* ln2    = (const float*)d_in[12];
    const float* wg     = (const float*)d_in[13];
    const float* wu     = (const float*)d_in[14];
    const float* wd     = (const float*)d_in[15];
    const float* normw  = (const float*)d_in[16];
    float* out = (float*)d_out;

    float *hid, *hnorm, *q, *kb, *vb, *sc, *at, *gb, *ub;
    cudaGetSymbolAddress((void**)&hid,   g_hid);
    cudaGetSymbolAddress((void**)&hnorm, g_hnorm);
    cudaGetSymbolAddress((void**)&q,     g_q);
    cudaGetSymbolAddress((void**)&kb,    g_kbuf);
    cudaGetSymbolAddress((void**)&vb,    g_vbuf);
    cudaGetSymbolAddress((void**)&sc,    g_scores);
    cudaGetSymbolAddress((void**)&at,    g_attn);
    cudaGetSymbolAddress((void**)&gb,    g_gate);
    cudaGetSymbolAddress((void**)&ub,    g_up);

    cudaMemcpyAsync(hid, embeds, sizeof(float) * Sn * Hn, cudaMemcpyDeviceToDevice);

    for (int i = 0; i < Ln; i++) {
        float* kc = out + (size_t)Sn * Hn + (size_t)i * 2 * NKVn * Tn * HDn;
        float* vc = kc + (size_t)NKVn * Tn * HDn;

        // pre-attention norm
        rmsnorm_kernel<<<Sn, 256>>>(hid, ln1 + (size_t)i * Hn, hnorm);

        // QKV projections
        launch_gemm<false>(hnorm, wq + (size_t)i * Hn * NHn * HDn, bq + (size_t)i * NHn * HDn,
                           nullptr, q, Sn, NHn * HDn, Hn, Hn, NHn * HDn, NHn * HDn,
                           0, 0, 0, 1, 1.f, 1);
        launch_gemm<false>(hnorm, wk + (size_t)i * Hn * NKVn * HDn, bk + (size_t)i * NKVn * HDn,
                           nullptr, kb, Sn, NKVn * HDn, Hn, Hn, NKVn * HDn, NKVn * HDn,
                           0, 0, 0, 1, 1.f, 1);
        launch_gemm<false>(hnorm, wv + (size_t)i * Hn * NKVn * HDn, bv + (size_t)i * NKVn * HDn,
                           nullptr, vb, Sn, NKVn * HDn, Hn, Hn, NKVn * HDn, NKVn * HDn,
                           0, 0, 0, 1, 1.f, 1);

        // RoPE + cache assembly (caches live directly in d_out)
        rope_q_kernel<<<dim3(Sn, NHn), 64>>>(q, pos);
        kv_cache_kernel<<<dim3(Tn, NKVn), HDn>>>(
            kb, vb,
            past_k + (size_t)i * NKVn * Pn * HDn,
            past_v + (size_t)i * NKVn * Pn * HDn,
            pos, kc, vc);

        // scores[h] = SCALE * Q_h (S x HD) @ K_{h/G}^T (HD x T)
        launch_gemm<true>(q, kc, nullptr, nullptr, sc,
                          Sn, Tn, HDn, NHn * HDn, HDn, Tn,
                          (long long)HDn, (long long)Tn * HDn, (long long)Sn * Tn,
                          Gn, SCALEn, NHn);

        softmax_kernel<<<dim3(Sn, NHn), 256>>>(sc, pos);

        // attn_out[h] = P_h (S x T) @ V_{h/G} (T x HD)
        launch_gemm<false>(sc, vc, nullptr, nullptr, at,
                           Sn, HDn, Tn, Tn, HDn, NHn * HDn,
                           (long long)Sn * Tn, (long long)Tn * HDn, (long long)HDn,
                           Gn, 1.f, NHn);

        // output projection + residual
        launch_gemm<false>(at, wo + (size_t)i * Hn * Hn, nullptr, hid, hid,
                           Sn, Hn, Hn, Hn, Hn, Hn, 0, 0, 0, 1, 1.f, 1);

        // MLP
        rmsnorm_kernel<<<Sn, 256>>>(hid, ln2 + (size_t)i * Hn, hnorm);
        launch_gemm<false>(hnorm, wg + (size_t)i * Hn * FFn, nullptr, nullptr, gb,
                           Sn, FFn, Hn, Hn, FFn, FFn, 0, 0, 0, 1, 1.f, 1);
        launch_gemm<false>(hnorm, wu + (size_t)i * Hn * FFn, nullptr, nullptr, ub,
                           Sn, FFn, Hn, Hn, FFn, FFn, 0, 0, 0, 1, 1.f, 1);
        silu_mul_kernel<<<(Sn * FFn / 4 + 255) / 256, 256>>>(gb, ub, Sn * FFn / 4);
        launch_gemm<false>(gb, wd + (size_t)i * FFn * Hn, nullptr, hid, hid,
                           Sn, Hn, FFn, FFn, Hn, Hn, 0, 0, 0, 1, 1.f, 1);
    }

    // final norm -> hidden output
    rmsnorm_kernel<<<Sn, 256>>>(hid, normw, out);
}

// round 5
// speedup vs baseline: 2.6896x; 2.6896x over previous
#include <cuda_runtime.h>
#include <cuda_bf16.h>
#include <math.h>
#include <stdint.h>

// ---------------- problem constants ----------------
#define Ln   2
#define Hn   2048
#define NHn  16
#define NKVn 2
#define HDn  128
#define Sn   1024
#define Pn   1024
#define FFn  5632
#define Tn   (Pn + Sn)       // 2048
#define Gn   (NHn / NKVn)    // 8
#define EPSn 1e-6f
#define SCALEn 0.08838834764831845f  // 1/sqrt(128)

typedef __nv_bfloat16 bf16;

// ---------------- device scratch (static, no allocation) ----------------
static __device__ float g_hid   [Sn * Hn];
static __device__ float g_q     [Sn * Hn];
static __device__ float g_kbuf  [Sn * NKVn * HDn];
static __device__ float g_vbuf  [Sn * NKVn * HDn];
static __device__ float g_scores[(size_t)NHn * Sn * Tn];   // 134 MB
static __device__ float g_gate  [(size_t)Sn * FFn];
static __device__ float g_up    [(size_t)Sn * FFn];

static __device__ bf16 g_hn_hi[Sn * Hn],  g_hn_lo[Sn * Hn];
static __device__ bf16 g_q_hi [Sn * Hn],  g_q_lo [Sn * Hn];
static __device__ bf16 g_k_hi [NKVn * Tn * HDn], g_k_lo [NKVn * Tn * HDn];
static __device__ bf16 g_vt_hi[NKVn * HDn * Tn], g_vt_lo[NKVn * HDn * Tn];
static __device__ bf16 g_p_hi [(size_t)NHn * Sn * Tn], g_p_lo [(size_t)NHn * Sn * Tn];
static __device__ bf16 g_at_hi[Sn * Hn],  g_at_lo[Sn * Hn];
static __device__ bf16 g_g_hi [(size_t)Sn * FFn], g_g_lo [(size_t)Sn * FFn];

// transposed+split weights: per layer [wq(2048x2048), wk(256x2048), wv(256x2048),
//  wo(2048x2048), wg(5632x2048), wu(5632x2048), wd(2048x5632)]  (all [N,K])
#define WL 44040192LL
#define WTOT (2 * WL)
static __device__ bf16 g_w_hi[WTOT], g_w_lo[WTOT];

// ---------------- small helpers ----------------
__device__ __forceinline__ float warpSum(float v) {
#pragma unroll
    for (int o = 16; o; o >>= 1) v += __shfl_xor_sync(0xffffffffu, v, o);
    return v;
}
__device__ __forceinline__ float warpMax(float v) {
#pragma unroll
    for (int o = 16; o; o >>= 1) v = fmaxf(v, __shfl_xor_sync(0xffffffffu, v, o));
    return v;
}
__device__ float blockSum256(float v) {
    __shared__ float sm[8]; __shared__ float res;
    v = warpSum(v);
    if ((threadIdx.x & 31) == 0) sm[threadIdx.x >> 5] = v;
    __syncthreads();
    float w = (threadIdx.x < 8) ? sm[threadIdx.x] : 0.f;
    w = warpSum(w);
    if (threadIdx.x == 0) res = w;
    __syncthreads();
    return res;
}
__device__ float blockMax256(float v) {
    __shared__ float sm[8]; __shared__ float res;
    v = warpMax(v);
    if ((threadIdx.x & 31) == 0) sm[threadIdx.x >> 5] = v;
    __syncthreads();
    float w = (threadIdx.x < 8) ? sm[threadIdx.x] : -1e30f;
    w = warpMax(w);
    if (threadIdx.x == 0) res = w;
    __syncthreads();
    return res;
}

__device__ __forceinline__ void split_bf16(float x, bf16& h, bf16& l) {
    h = __float2bfloat16(x);
    l = __float2bfloat16(x - __bfloat162float(h));
}

// ---------------- PTX wrappers (all plain sm_80+ features) ----------------
__device__ __forceinline__ uint32_t smem_u32(const void* p) {
    uint32_t a;
    asm("{ .reg .u64 t; cvta.to.shared.u64 t, %1; cvt.u32.u64 %0, t; }" : "=r"(a) : "l"(p));
    return a;
}
__device__ __forceinline__ void cpa16(uint32_t d, const void* s) {
    asm volatile("cp.async.cg.shared.global [%0], [%1], 16;" :: "r"(d), "l"(s));
}
__device__ __forceinline__ void cp_commit() {
    asm volatile("cp.async.commit_group;" ::: "memory");
}
__device__ __forceinline__ void cp_wait1() {
    asm volatile("cp.async.wait_group 1;" ::: "memory");
}
__device__ __forceinline__ void cp_wait0() {
    asm volatile("cp.async.wait_group 0;" ::: "memory");
}
__device__ __forceinline__ void ldm4(uint32_t* r, uint32_t a) {
    asm volatile("ldmatrix.sync.aligned.m8n8.x4.shared.b16 {%0,%1,%2,%3}, [%4];"
        : "=r"(r[0]), "=r"(r[1]), "=r"(r[2]), "=r"(r[3]) : "r"(a));
}
__device__ __forceinline__ void mma16816(float* c, const uint32_t* a, const uint32_t* b) {
    asm volatile(
        "mma.sync.aligned.m16n8k16.row.col.f32.bf16.bf16.f32 "
        "{%0,%1,%2,%3}, {%4,%5,%6,%7}, {%8,%9}, {%0,%1,%2,%3};"
        : "+f"(c[0]), "+f"(c[1]), "+f"(c[2]), "+f"(c[3])
        : "r"(a[0]), "r"(a[1]), "r"(a[2]), "r"(a[3]), "r"(b[0]), "r"(b[1]));
}

// ---------------- tensor-core GEMM (mma.sync bf16, 3-way split) ----------------
// C[M,N] = alpha * A[M,K] @ B[N,K]^T (+bias)(+Res). A/B are bf16 hi/lo pairs.
// Tile 128x128, K-chunk 32, 8 warps (2x4), warp tile 64x32.
// OUTF32=1: fp32 Cf (bias/Res/alpha). OUTF32=0: bf16 hi/lo out (alpha applied).
#define AST  40                        // smem row stride in bf16 (80 B, conflict-free)
#define TILEB (128 * AST * 2)          // 10240 B per plane
#define STAGEB (4 * TILEB)             // Ah, Al, Bh, Bl

template<int OUTF32>
__global__ void __launch_bounds__(256, 1)
mma_gemm(const bf16* __restrict__ Ah, const bf16* __restrict__ Al,
         const bf16* __restrict__ Bh, const bf16* __restrict__ Bl,
         const float* __restrict__ bias, const float* __restrict__ Res,
         float* __restrict__ Cf, bf16* __restrict__ Chi, bf16* __restrict__ Clo,
         int K, int lda, int ldb, int ldc,
         long long sA, long long sB, long long sC, int bdiv, float alpha)
{
    extern __shared__ char smc[];
    const int tid = threadIdx.x;
    const int lane = tid & 31;
    const int wid = tid >> 5;
    const int wm = wid >> 2;           // 0..1
    const int wn = wid & 3;            // 0..3
    const long long z = blockIdx.z;

    Ah += z * sA; Al += z * sA;
    Bh += (z / bdiv) * sB; Bl += (z / bdiv) * sB;
    const int row0 = blockIdx.y * 128;
    const int col0 = blockIdx.x * 128;

    const uint32_t smb = smem_u32(smc);

    float acc[4][4][4];
#pragma unroll
    for (int i = 0; i < 4; i++)
#pragma unroll
        for (int j = 0; j < 4; j++)
#pragma unroll
            for (int e = 0; e < 4; e++) acc[i][j][e] = 0.f;

    const int nk = K >> 5;

    // ---- async tile loader: chunk i -> stage i&1 ----
    auto load_tile = [&](int i) {
        const int k0 = i << 5;
        const uint32_t sb = smb + (i & 1) * STAGEB;
#pragma unroll
        for (int c = tid; c < 512; c += 256) {
            const int r = c >> 2, sg = c & 3;
            const uint32_t d = sb + r * (AST * 2) + sg * 16;
            const size_t ga = (size_t)(row0 + r) * lda + k0 + sg * 8;
            const size_t gb = (size_t)(col0 + r) * ldb + k0 + sg * 8;
            cpa16(d,             Ah + ga);
            cpa16(d + TILEB,     Al + ga);
            cpa16(d + 2 * TILEB, Bh + gb);
            cpa16(d + 3 * TILEB, Bl + gb);
        }
    };

    load_tile(0);
    cp_commit();

    for (int i = 0; i < nk; i++) {
        if (i + 1 < nk) { load_tile(i + 1); cp_commit(); cp_wait1(); }
        else            { cp_wait0(); }
        __syncthreads();

        const uint32_t sb = smb + (i & 1) * STAGEB;
#pragma unroll
        for (int ks = 0; ks < 2; ks++) {
            uint32_t ah[4][4], al[4][4], bh[4][2], bl[4][2];
            // A fragments: matrices (m0,k0),(m0+8,k0),(m0,k0+8),(m0+8,k0+8)
            const int acol = ks * 32 + ((lane >> 4) & 1) * 16;   // bytes
#pragma unroll
            for (int mt = 0; mt < 4; mt++) {
                const int row = wm * 64 + mt * 16 + ((lane >> 3) & 1) * 8 + (lane & 7);
                const uint32_t a = sb + row * (AST * 2) + acol;
                ldm4(ah[mt], a);
                ldm4(al[mt], a + TILEB);
            }
            // B fragments: x4 covers two n-tiles (n,k0),(n,k0+8),(n+8,k0),(n+8,k0+8)
            const int bcol = ks * 32 + ((lane >> 3) & 1) * 16;   // bytes
#pragma unroll
            for (int p = 0; p < 2; p++) {
                const int row = wn * 32 + p * 16 + ((lane >> 4) & 1) * 8 + (lane & 7);
                const uint32_t a = sb + 2 * TILEB + row * (AST * 2) + bcol;
                uint32_t r[4];
                ldm4(r, a);
                bh[2*p][0] = r[0]; bh[2*p][1] = r[1];
                bh[2*p+1][0] = r[2]; bh[2*p+1][1] = r[3];
                ldm4(r, a + TILEB);
                bl[2*p][0] = r[0]; bl[2*p][1] = r[1];
                bl[2*p+1][0] = r[2]; bl[2*p+1][1] = r[3];
            }
#pragma unroll
            for (int mt = 0; mt < 4; mt++)
#pragma unroll
                for (int nt = 0; nt < 4; nt++) {
                    mma16816(acc[mt][nt], ah[mt], bh[nt]);
                    mma16816(acc[mt][nt], ah[mt], bl[nt]);
                    mma16816(acc[mt][nt], al[mt], bh[nt]);
                }
        }
        __syncthreads();
    }

    // ---- epilogue ----
#pragma unroll
    for (int mt = 0; mt < 4; mt++) {
#pragma unroll
        for (int nt = 0; nt < 4; nt++) {
            const int row = row0 + wm * 64 + mt * 16 + (lane >> 2);
            const int col = col0 + wn * 32 + nt * 8 + (lane & 3) * 2;
            float v0 = acc[mt][nt][0] * alpha;
            float v1 = acc[mt][nt][1] * alpha;
            float v2 = acc[mt][nt][2] * alpha;
            float v3 = acc[mt][nt][3] * alpha;
            const long long o0 = z * sC + (long long)row * ldc + col;
            const long long o1 = o0 + 8LL * ldc;
            if (OUTF32) {
                if (bias) {
                    float b0 = __ldg(bias + col), b1 = __ldg(bias + col + 1);
                    v0 += b0; v1 += b1; v2 += b0; v3 += b1;
                }
                if (Res) {
                    float2 r0 = *reinterpret_cast<const float2*>(Res + o0);
                    float2 r1 = *reinterpret_cast<const float2*>(Res + o1);
                    v0 += r0.x; v1 += r0.y; v2 += r1.x; v3 += r1.y;
                }
                *reinterpret_cast<float2*>(Cf + o0) = make_float2(v0, v1);
                *reinterpret_cast<float2*>(Cf + o1) = make_float2(v2, v3);
            } else {
                bf16 h0,l0,h1,l1,h2,l2,h3,l3;
                split_bf16(v0,h0,l0); split_bf16(v1,h1,l1);
                split_bf16(v2,h2,l2); split_bf16(v3,h3,l3);
                __nv_bfloat162 hh0(h0,h1), hh1(h2,h3), ll0(l0,l1), ll1(l2,l3);
                *reinterpret_cast<uint32_t*>(Chi + o0) = *reinterpret_cast<uint32_t*>(&hh0);
                *reinterpret_cast<uint32_t*>(Chi + o1) = *reinterpret_cast<uint32_t*>(&hh1);
                *reinterpret_cast<uint32_t*>(Clo + o0) = *reinterpret_cast<uint32_t*>(&ll0);
                *reinterpret_cast<uint32_t*>(Clo + o1) = *reinterpret_cast<uint32_t*>(&ll1);
            }
        }
    }
}

// ---------------- weight transpose + split: in[K,N] fp32 -> out[N,K] bf16 hi/lo ----------------
__global__ void __launch_bounds__(256)
convT_kernel(const float* __restrict__ in, bf16* __restrict__ hi, bf16* __restrict__ lo,
             int K, int N)
{
    __shared__ float t[32][33];
    int k0 = blockIdx.y * 32, n0 = blockIdx.x * 32;
    int x = threadIdx.x & 31, y = threadIdx.x >> 5;  // 32 x 8
#pragma unroll
    for (int i = 0; i < 32; i += 8)
        t[y + i][x] = in[(size_t)(k0 + y + i) * N + n0 + x];
    __syncthreads();
#pragma unroll
    for (int i = 0; i < 32; i += 8) {
        float v = t[x][y + i];
        bf16 h, l; split_bf16(v, h, l);
        size_t o = (size_t)(n0 + y + i) * K + k0 + x;
        hi[o] = h; lo[o] = l;
    }
}

// ---------------- RMSNorm: MODE 0 -> fp32 out, MODE 1 -> bf16 hi/lo ----------------
template<int MODE>
__global__ void __launch_bounds__(256)
rmsnorm_kernel(const float* __restrict__ x, const float* __restrict__ w,
               float* __restrict__ yf, bf16* __restrict__ yh, bf16* __restrict__ yl)
{
    int s = blockIdx.x;
    const float* row = x + (size_t)s * Hn;
    float4 buf[2];
    float ss = 0.f;
#pragma unroll
    for (int it = 0; it < 2; it++) {
        int j = (it * 256 + threadIdx.x) * 4;
        float4 v = *reinterpret_cast<const float4*>(row + j);
        buf[it] = v;
        ss += v.x * v.x + v.y * v.y + v.z * v.z + v.w * v.w;
    }
    ss = blockSum256(ss);
    float inv = rsqrtf(ss * (1.0f / Hn) + EPSn);
#pragma unroll
    for (int it = 0; it < 2; it++) {
        int j = (it * 256 + threadIdx.x) * 4;
        float4 wv = *reinterpret_cast<const float4*>(w + j);
        float o0 = buf[it].x * inv * wv.x;
        float o1 = buf[it].y * inv * wv.y;
        float o2 = buf[it].z * inv * wv.z;
        float o3 = buf[it].w * inv * wv.w;
        if (MODE == 0) {
            *reinterpret_cast<float4*>(yf + (size_t)s * Hn + j) = make_float4(o0, o1, o2, o3);
        } else {
            bf16 h0,l0,h1,l1,h2,l2,h3,l3;
            split_bf16(o0,h0,l0); split_bf16(o1,h1,l1);
            split_bf16(o2,h2,l2); split_bf16(o3,h3,l3);
            __nv_bfloat162 hh0(h0,h1), hh1(h2,h3), ll0(l0,l1), ll1(l2,l3);
            uint2 uh = make_uint2(*reinterpret_cast<uint32_t*>(&hh0), *reinterpret_cast<uint32_t*>(&hh1));
            uint2 ul = make_uint2(*reinterpret_cast<uint32_t*>(&ll0), *reinterpret_cast<uint32_t*>(&ll1));
            *reinterpret_cast<uint2*>(yh + (size_t)s * Hn + j) = uh;
            *reinterpret_cast<uint2*>(yl + (size_t)s * Hn + j) = ul;
        }
    }
}

// ---------------- RoPE for Q: fp32 in -> bf16 hi/lo out ----------------
__global__ void rope_q_kernel(const float* __restrict__ q, const int* __restrict__ pos,
                              bf16* __restrict__ qh, bf16* __restrict__ ql)
{
    int s = blockIdx.x, h = blockIdx.y, d = threadIdx.x; // d in [0,64)
    double ang = (double)pos[s] * exp(-(double)d / 64.0 * 13.815510557964274);
    double sd, cd; sincos(ang, &sd, &cd);
    float c = (float)cd, sn = (float)sd;
    size_t base = ((size_t)s * NHn + h) * HDn;
    float x1 = q[base + d], x2 = q[base + d + 64];
    float v1 = x1 * c - x2 * sn;
    float v2 = x2 * c + x1 * sn;
    bf16 hh, ll;
    split_bf16(v1, hh, ll); qh[base + d] = hh;      ql[base + d] = ll;
    split_bf16(v2, hh, ll); qh[base + d + 64] = hh; ql[base + d + 64] = ll;
}

// ---------------- K/V cache: fp32 caches (to d_out) + bf16 hi/lo K + transposed V ----------------
__global__ void kv_cache_kernel(const float* __restrict__ kbuf, const float* __restrict__ vbuf,
                                const float* __restrict__ pastk, const float* __restrict__ pastv,
                                const int* __restrict__ pos,
                                float* __restrict__ kc, float* __restrict__ vc,
                                bf16* __restrict__ kh, bf16* __restrict__ kl,
                                bf16* __restrict__ vth, bf16* __restrict__ vtl)
{
    int t = blockIdx.x, kv = blockIdx.y, d = threadIdx.x; // d in [0,128)
    size_t oidx = ((size_t)kv * Tn + t) * HDn + d;
    float kval, vval;
    if (t < Pn) {
        size_t pidx = ((size_t)kv * Pn + t) * HDn + d;
        kval = pastk[pidx];
        vval = pastv[pidx];
    } else {
        int s = t - Pn;
        const float* kr = kbuf + (size_t)s * (NKVn * HDn) + kv * HDn;
        int dr = d & 63;
        double ang = (double)pos[s] * exp(-(double)dr / 64.0 * 13.815510557964274);
        double sd, cd; sincos(ang, &sd, &cd);
        float c = (float)cd, sn = (float)sd;
        if (d < 64) kval = kr[d] * c - kr[d + 64] * sn;
        else        kval = kr[d] * c + kr[d - 64] * sn;
        vval = vbuf[(size_t)s * (NKVn * HDn) + kv * HDn + d];
    }
    kc[oidx] = kval;
    vc[oidx] = vval;
    bf16 h, l;
    split_bf16(kval, h, l); kh[oidx] = h; kl[oidx] = l;
    split_bf16(vval, h, l);
    size_t tidx = ((size_t)kv * HDn + d) * Tn + t;
    vth[tidx] = h; vtl[tidx] = l;
}

// ---------------- masked softmax: fp32 scores -> bf16 hi/lo P ----------------
__global__ void __launch_bounds__(256)
softmax_kernel(const float* __restrict__ scores, const int* __restrict__ pos,
               bf16* __restrict__ ph, bf16* __restrict__ pl)
{
    int s = blockIdx.x, h = blockIdx.y;
    size_t rbase = ((size_t)h * Sn + s) * Tn;
    const float* row = scores + rbase;
    int lim = pos[s];
    int tid = threadIdx.x;
    float v[8];
    float m = -1e30f;
#pragma unroll
    for (int it = 0; it < 2; it++) {
        int t0 = (it * 256 + tid) * 4;
        float4 x = *reinterpret_cast<const float4*>(row + t0);
        float xs[4] = {x.x, x.y, x.z, x.w};
#pragma unroll
        for (int e = 0; e < 4; e++) {
            float val = (t0 + e <= lim) ? xs[e] : -1e30f;
            v[it * 4 + e] = val;
            m = fmaxf(m, val);
        }
    }
    m = blockMax256(m);
    float sum = 0.f;
#pragma unroll
    for (int e = 0; e < 8; e++) {
        float ex = (v[e] > -1e29f) ? expf(v[e] - m) : 0.f;
        v[e] = ex;
        sum += ex;
    }
    sum = blockSum256(sum);
    float inv = 1.f / sum;
#pragma unroll
    for (int it = 0; it < 2; it++) {
        int t0 = (it * 256 + tid) * 4;
        bf16 h0,l0,h1,l1,h2,l2,h3,l3;
        split_bf16(v[it*4+0] * inv, h0, l0);
        split_bf16(v[it*4+1] * inv, h1, l1);
        split_bf16(v[it*4+2] * inv, h2, l2);
        split_bf16(v[it*4+3] * inv, h3, l3);
        __nv_bfloat162 hh0(h0,h1), hh1(h2,h3), ll0(l0,l1), ll1(l2,l3);
        uint2 uh = make_uint2(*reinterpret_cast<uint32_t*>(&hh0), *reinterpret_cast<uint32_t*>(&hh1));
        uint2 ul = make_uint2(*reinterpret_cast<uint32_t*>(&ll0), *reinterpret_cast<uint32_t*>(&ll1));
        *reinterpret_cast<uint2*>(ph + rbase + t0) = uh;
        *reinterpret_cast<uint2*>(pl + rbase + t0) = ul;
    }
}

// ---------------- SiLU(gate) * up -> bf16 hi/lo ----------------
__global__ void silu_mul_kernel(const float* __restrict__ g, const float* __restrict__ u,
                                bf16* __restrict__ oh, bf16* __restrict__ ol, int n4)
{
    int i = blockIdx.x * blockDim.x + threadIdx.x;
    if (i < n4) {
        float4 gv = reinterpret_cast<const float4*>(g)[i];
        float4 uv = reinterpret_cast<const float4*>(u)[i];
        float r0 = gv.x / (1.f + expf(-gv.x)) * uv.x;
        float r1 = gv.y / (1.f + expf(-gv.y)) * uv.y;
        float r2 = gv.z / (1.f + expf(-gv.z)) * uv.z;
        float r3 = gv.w / (1.f + expf(-gv.w)) * uv.w;
        bf16 h0,l0,h1,l1,h2,l2,h3,l3;
        split_bf16(r0,h0,l0); split_bf16(r1,h1,l1);
        split_bf16(r2,h2,l2); split_bf16(r3,h3,l3);
        __nv_bfloat162 hh0(h0,h1), hh1(h2,h3), ll0(l0,l1), ll1(l2,l3);
        uint2 uh = make_uint2(*reinterpret_cast<uint32_t*>(&hh0), *reinterpret_cast<uint32_t*>(&hh1));
        uint2 ul = make_uint2(*reinterpret_cast<uint32_t*>(&ll0), *reinterpret_cast<uint32_t*>(&ll1));
        *reinterpret_cast<uint2*>(oh + (size_t)i * 4) = uh;
        *reinterpret_cast<uint2*>(ol + (size_t)i * 4) = ul;
    }
}

// ---------------- host-side launch helper ----------------
template<int OUTF32>
static void mmagemm(const bf16* Ah, const bf16* Al, const bf16* Bh, const bf16* Bl,
                    const float* bias, const float* Res,
                    float* Cf, bf16* Chi, bf16* Clo,
                    int M, int N, int K, int lda, int ldb, int ldc,
                    long long sA, long long sB, long long sC, int bdiv, float alpha, int batch)
{
    dim3 grid(N / 128, M / 128, batch);
    mma_gemm<OUTF32><<<grid, 256, 2 * STAGEB>>>(Ah, Al, Bh, Bl, bias, Res, Cf, Chi, Clo,
                                                K, lda, ldb, ldc, sA, sB, sC, bdiv, alpha);
}

extern "C" void kernel_launch(void* const* d_in, const int* in_sizes, int n_in,
                              void* d_out, int out_size)
{
    (void)in_sizes; (void)n_in; (void)out_size;
    const float* embeds = (const float*)d_in[0];
    const int*   pos    = (const int*)  d_in[1];
    const float* past_k = (const float*)d_in[2];
    const float* past_v = (const float*)d_in[3];
    const float* ln1    = (const float*)d_in[4];
    const float* wq     = (const float*)d_in[5];
    const float* bq     = (const float*)d_in[6];
    const float* wk     = (const float*)d_in[7];
    const float* bk     = (const float*)d_in[8];
    const float* wv     = (const float*)d_in[9];
    const float* bv     = (const float*)d_in[10];
    const float* wo     = (const float*)d_in[11];
    const float* ln2    = (const float*)d_in[12];
    const float* wg     = (const float*)d_in[13];
    const float* wu     = (const float*)d_in[14];
    const float* wd     = (const float*)d_in[15];
    const float* normw  = (const float*)d_in[16];
    float* out = (float*)d_out;

    cudaFuncSetAttribute(mma_gemm<1>, cudaFuncAttributeMaxDynamicSharedMemorySize, 2 * STAGEB);
    cudaFuncSetAttribute(mma_gemm<0>, cudaFuncAttributeMaxDynamicSharedMemorySize, 2 * STAGEB);

    float *hid, *q, *kb, *vb, *sc, *gb, *ub;
    cudaGetSymbolAddress((void**)&hid, g_hid);
    cudaGetSymbolAddress((void**)&q,   g_q);
    cudaGetSymbolAddress((void**)&kb,  g_kbuf);
    cudaGetSymbolAddress((void**)&vb,  g_vbuf);
    cudaGetSymbolAddress((void**)&sc,  g_scores);
    cudaGetSymbolAddress((void**)&gb,  g_gate);
    cudaGetSymbolAddress((void**)&ub,  g_up);
    bf16 *hnh,*hnl,*qh,*ql,*kh,*kl,*vth,*vtl,*ph,*pl,*ath,*atl,*gh,*gl,*wh,*wl;
    cudaGetSymbolAddress((void**)&hnh, g_hn_hi); cudaGetSymbolAddress((void**)&hnl, g_hn_lo);
    cudaGetSymbolAddress((void**)&qh,  g_q_hi);  cudaGetSymbolAddress((void**)&ql,  g_q_lo);
    cudaGetSymbolAddress((void**)&kh,  g_k_hi);  cudaGetSymbolAddress((void**)&kl,  g_k_lo);
    cudaGetSymbolAddress((void**)&vth, g_vt_hi); cudaGetSymbolAddress((void**)&vtl, g_vt_lo);
    cudaGetSymbolAddress((void**)&ph,  g_p_hi);  cudaGetSymbolAddress((void**)&pl,  g_p_lo);
    cudaGetSymbolAddress((void**)&ath, g_at_hi); cudaGetSymbolAddress((void**)&atl, g_at_lo);
    cudaGetSymbolAddress((void**)&gh,  g_g_hi);  cudaGetSymbolAddress((void**)&gl,  g_g_lo);
    cudaGetSymbolAddress((void**)&wh,  g_w_hi);  cudaGetSymbolAddress((void**)&wl,  g_w_lo);

    // per-layer offsets into transposed weight store
    const long long OQ = 0, OK = 4194304, OV = 4718592, OO = 5242880,
                    OG = 9437184, OU = 20971520, OD = 32505856;

    // ---- transpose + split all weights ----
    dim3 cb(256);
    for (int l = 0; l < Ln; l++) {
        long long base = (long long)l * WL;
        convT_kernel<<<dim3(2048/32, 2048/32), cb>>>(wq + (size_t)l*Hn*2048, wh + base + OQ, wl + base + OQ, Hn, 2048);
        convT_kernel<<<dim3(256/32,  2048/32), cb>>>(wk + (size_t)l*Hn*256,  wh + base + OK, wl + base + OK, Hn, 256);
        convT_kernel<<<dim3(256/32,  2048/32), cb>>>(wv + (size_t)l*Hn*256,  wh + base + OV, wl + base + OV, Hn, 256);
        convT_kernel<<<dim3(2048/32, 2048/32), cb>>>(wo + (size_t)l*Hn*Hn,   wh + base + OO, wl + base + OO, Hn, 2048);
        convT_kernel<<<dim3(5632/32, 2048/32), cb>>>(wg + (size_t)l*Hn*FFn,  wh + base + OG, wl + base + OG, Hn, FFn);
        convT_kernel<<<dim3(5632/32, 2048/32), cb>>>(wu + (size_t)l*Hn*FFn,  wh + base + OU, wl + base + OU, Hn, FFn);
        convT_kernel<<<dim3(2048/32, 5632/32), cb>>>(wd + (size_t)l*FFn*Hn,  wh + base + OD, wl + base + OD, FFn, 2048);
    }

    cudaMemcpyAsync(hid, embeds, sizeof(float) * Sn * Hn, cudaMemcpyDeviceToDevice);

    for (int l = 0; l < Ln; l++) {
        long long base = (long long)l * WL;
        float* kc = out + (size_t)Sn * Hn + (size_t)l * 2 * NKVn * Tn * HDn;
        float* vc = kc + (size_t)NKVn * Tn * HDn;

        // pre-attention norm -> bf16 hi/lo
        rmsnorm_kernel<1><<<Sn, 256>>>(hid, ln1 + (size_t)l * Hn, nullptr, hnh, hnl);

        // QKV projections (fp32 out)
        mmagemm<1>(hnh, hnl, wh + base + OQ, wl + base + OQ, bq + (size_t)l*2048, nullptr,
                   q, nullptr, nullptr, Sn, 2048, Hn, Hn, Hn, 2048, 0, 0, 0, 1, 1.f, 1);
        mmagemm<1>(hnh, hnl, wh + base + OK, wl + base + OK, bk + (size_t)l*256, nullptr,
                   kb, nullptr, nullptr, Sn, 256, Hn, Hn, Hn, 256, 0, 0, 0, 1, 1.f, 1);
        mmagemm<1>(hnh, hnl, wh + base + OV, wl + base + OV, bv + (size_t)l*256, nullptr,
                   vb, nullptr, nullptr, Sn, 256, Hn, Hn, Hn, 256, 0, 0, 0, 1, 1.f, 1);

        // RoPE Q -> bf16 hi/lo; KV cache (fp32 to d_out + bf16 hi/lo, V transposed)
        rope_q_kernel<<<dim3(Sn, NHn), 64>>>(q, pos, qh, ql);
        kv_cache_kernel<<<dim3(Tn, NKVn), HDn>>>(
            kb, vb,
            past_k + (size_t)l * NKVn * Pn * HDn,
            past_v + (size_t)l * NKVn * Pn * HDn,
            pos, kc, vc, kh, kl, vth, vtl);

        // scores[h] = SCALE * Q_h @ K_{h/G}^T   (fp32 out)
        mmagemm<1>(qh, ql, kh, kl, nullptr, nullptr, sc, nullptr, nullptr,
                   Sn, Tn, HDn, NHn*HDn, HDn, Tn,
                   (long long)HDn, (long long)Tn*HDn, (long long)Sn*Tn, Gn, SCALEn, NHn);

        softmax_kernel<<<dim3(Sn, NHn), 256>>>(sc, pos, ph, pl);

        // attn_out[h] = P_h @ V_{h/G}  (B = transposed V [HD,T]), bf16 hi/lo out
        mmagemm<0>(ph, pl, vth, vtl, nullptr, nullptr, nullptr, ath, atl,
                   Sn, HDn, Tn, Tn, Tn, NHn*HDn,
                   (long long)Sn*Tn, (long long)HDn*Tn, (long long)HDn, Gn, 1.f, NHn);

        // output projection + residual (fp32)
        mmagemm<1>(ath, atl, wh + base + OO, wl + base + OO, nullptr, hid,
                   hid, nullptr, nullptr, Sn, Hn, Hn, Hn, Hn, Hn, 0, 0, 0, 1, 1.f, 1);

        // MLP
        rmsnorm_kernel<1><<<Sn, 256>>>(hid, ln2 + (size_t)l * Hn, nullptr, hnh, hnl);
        mmagemm<1>(hnh, hnl, wh + base + OG, wl + base + OG, nullptr, nullptr,
                   gb, nullptr, nullptr, Sn, FFn, Hn, Hn, Hn, FFn, 0, 0, 0, 1, 1.f, 1);
        mmagemm<1>(hnh, hnl, wh + base + OU, wl + base + OU, nullptr, nullptr,
                   ub, nullptr, nullptr, Sn, FFn, Hn, Hn, Hn, FFn, 0, 0, 0, 1, 1.f, 1);
        silu_mul_kernel<<<(Sn * FFn / 4 + 255) / 256, 256>>>(gb, ub, gh, gl, Sn * FFn / 4);
        mmagemm<1>(gh, gl, wh + base + OD, wl + base + OD, nullptr, hid,
                   hid, nullptr, nullptr, Sn, Hn, FFn, FFn, FFn, Hn, 0, 0, 0, 1, 1.f, 1);
    }

    // final norm -> fp32 hidden output
    rmsnorm_kernel<0><<<Sn, 256>>>(hid, normw, out, nullptr, nullptr);
}

// round 8
// speedup vs baseline: 3.1397x; 1.1674x over previous
#include <cuda_runtime.h>
#include <cuda_bf16.h>
#include <math.h>
#include <stdint.h>

// ---------------- problem constants ----------------
#define Ln   2
#define Hn   2048
#define NHn  16
#define NKVn 2
#define HDn  128
#define Sn   1024
#define Pn   1024
#define FFn  5632
#define Tn   (Pn + Sn)       // 2048
#define Gn   (NHn / NKVn)    // 8
#define EPSn 1e-6f
#define SCALEn 0.08838834764831845f  // 1/sqrt(128)

typedef __nv_bfloat16 bf16;

// ---------------- device scratch (static, no allocation) ----------------
static __device__ float g_hid   [Sn * Hn];
static __device__ float g_qkv   [Sn * 2560];
static __device__ float g_scores[(size_t)NHn * Sn * Tn];      // 134 MB
static __device__ float g_gateup[(size_t)Sn * (2 * FFn)];     // 46 MB
static __device__ float g_bqkv  [2560];

static __device__ bf16 g_hn_hi[Sn * Hn],  g_hn_lo[Sn * Hn];
static __device__ bf16 g_q_hi [Sn * Hn],  g_q_lo [Sn * Hn];
static __device__ bf16 g_k_hi [NKVn * Tn * HDn], g_k_lo [NKVn * Tn * HDn];
static __device__ bf16 g_vt_hi[NKVn * HDn * Tn], g_vt_lo[NKVn * HDn * Tn];
static __device__ bf16 g_p_hi [(size_t)NHn * Sn * Tn], g_p_lo [(size_t)NHn * Sn * Tn];
static __device__ bf16 g_at_hi[Sn * Hn],  g_at_lo[Sn * Hn];
static __device__ bf16 g_g_hi [(size_t)Sn * FFn], g_g_lo [(size_t)Sn * FFn];

// transposed+split weights: per layer [wq(2048x2048), wk(256x2048), wv(256x2048),
//  wo(2048x2048), wg(5632x2048), wu(5632x2048), wd(2048x5632)]  (all [N,K])
#define WL 44040192LL
#define WTOT (2 * WL)
static __device__ bf16 g_w_hi[WTOT], g_w_lo[WTOT];

// ---------------- small helpers ----------------
__device__ __forceinline__ float warpSum(float v) {
#pragma unroll
    for (int o = 16; o; o >>= 1) v += __shfl_xor_sync(0xffffffffu, v, o);
    return v;
}
__device__ __forceinline__ float warpMax(float v) {
#pragma unroll
    for (int o = 16; o; o >>= 1) v = fmaxf(v, __shfl_xor_sync(0xffffffffu, v, o));
    return v;
}
__device__ float blockSum256(float v) {
    __shared__ float sm[8]; __shared__ float res;
    v = warpSum(v);
    if ((threadIdx.x & 31) == 0) sm[threadIdx.x >> 5] = v;
    __syncthreads();
    float w = (threadIdx.x < 8) ? sm[threadIdx.x] : 0.f;
    w = warpSum(w);
    if (threadIdx.x == 0) res = w;
    __syncthreads();
    return res;
}
__device__ float blockMax256(float v) {
    __shared__ float sm[8]; __shared__ float res;
    v = warpMax(v);
    if ((threadIdx.x & 31) == 0) sm[threadIdx.x >> 5] = v;
    __syncthreads();
    float w = (threadIdx.x < 8) ? sm[threadIdx.x] : -1e30f;
    w = warpMax(w);
    if (threadIdx.x == 0) res = w;
    __syncthreads();
    return res;
}

__device__ __forceinline__ void split_bf16(float x, bf16& h, bf16& l) {
    h = __float2bfloat16(x);
    l = __float2bfloat16(x - __bfloat162float(h));
}

// ---------------- PTX wrappers (plain sm_80+ features only) ----------------
__device__ __forceinline__ uint32_t smem_u32(const void* p) {
    uint32_t a;
    asm("{ .reg .u64 t; cvta.to.shared.u64 t, %1; cvt.u32.u64 %0, t; }" : "=r"(a) : "l"(p));
    return a;
}
__device__ __forceinline__ void cpa16(uint32_t d, const void* s) {
    asm volatile("cp.async.cg.shared.global [%0], [%1], 16;" :: "r"(d), "l"(s));
}
__device__ __forceinline__ void cp_commit() {
    asm volatile("cp.async.commit_group;" ::: "memory");
}
__device__ __forceinline__ void cp_wait2() {
    asm volatile("cp.async.wait_group 2;" ::: "memory");
}
__device__ __forceinline__ void cp_wait1() {
    asm volatile("cp.async.wait_group 1;" ::: "memory");
}
__device__ __forceinline__ void cp_wait0() {
    asm volatile("cp.async.wait_group 0;" ::: "memory");
}
__device__ __forceinline__ void ldm4(uint32_t* r, uint32_t a) {
    asm volatile("ldmatrix.sync.aligned.m8n8.x4.shared.b16 {%0,%1,%2,%3}, [%4];"
        : "=r"(r[0]), "=r"(r[1]), "=r"(r[2]), "=r"(r[3]) : "r"(a));
}
__device__ __forceinline__ void mma16816(float* c, const uint32_t* a, const uint32_t* b) {
    asm volatile(
        "mma.sync.aligned.m16n8k16.row.col.f32.bf16.bf16.f32 "
        "{%0,%1,%2,%3}, {%4,%5,%6,%7}, {%8,%9}, {%0,%1,%2,%3};"
        : "+f"(c[0]), "+f"(c[1]), "+f"(c[2]), "+f"(c[3])
        : "r"(a[0]), "r"(a[1]), "r"(a[2]), "r"(a[3]), "r"(b[0]), "r"(b[1]));
}

// ---------------- tensor-core GEMM (mma.sync bf16, 3-way split, 3-stage pipe) ----------------
// C[M,N] = alpha * A[M,K] @ B[N,K]^T (+bias)(+Res). A/B are bf16 hi/lo pairs.
// Tile 128x128, K-chunk 32, 8 warps (2x4), warp tile 64x32.
// OUTF32=1: fp32 Cf (bias/Res/alpha). OUTF32=0: bf16 hi/lo out (alpha applied).
// CAUSAL=0 none; 1 skip fully-masked tiles (scores); 2 clip K to valid keys (P*V).
#define AST  40                        // smem row stride in bf16 (80 B)
#define TILEB (128 * AST * 2)          // 10240 B per plane
#define STAGEB (4 * TILEB)             // Ah, Al, Bh, Bl
#define NSTAGE 3

template<int OUTF32, int CAUSAL>
__global__ void __launch_bounds__(256, 1)
mma_gemm(const bf16* __restrict__ Ah, const bf16* __restrict__ Al,
         const bf16* __restrict__ Bh, const bf16* __restrict__ Bl,
         const float* __restrict__ bias, const float* __restrict__ Res,
         float* __restrict__ Cf, bf16* __restrict__ Chi, bf16* __restrict__ Clo,
         int K, int lda, int ldb, int ldc,
         long long sA, long long sB, long long sC, int bdiv, float alpha)
{
    extern __shared__ char smc[];
    const int tid = threadIdx.x;
    const int lane = tid & 31;
    const int wid = tid >> 5;
    const int wm = wid >> 2;           // 0..1
    const int wn = wid & 3;            // 0..3
    const long long z = blockIdx.z;
    const int row0 = blockIdx.y * 128;
    const int col0 = blockIdx.x * 128;

    if (CAUSAL == 1 && col0 >= Pn + row0 + 128) return;   // fully masked tile

    Ah += z * sA; Al += z * sA;
    Bh += (z / bdiv) * sB; Bl += (z / bdiv) * sB;

    const uint32_t smb = smem_u32(smc);

    float acc[4][4][4];
#pragma unroll
    for (int i = 0; i < 4; i++)
#pragma unroll
        for (int j = 0; j < 4; j++)
#pragma unroll
            for (int e = 0; e < 4; e++) acc[i][j][e] = 0.f;

    int Keff = (CAUSAL == 2) ? min(K, Pn + 128 + row0) : K;
    const int nk = Keff >> 5;

    // ---- async tile loader: chunk i -> stage i%3 ----
    auto load_tile = [&](int i) {
        const int k0 = i << 5;
        const uint32_t sb = smb + (i % NSTAGE) * STAGEB;
#pragma unroll
        for (int c = tid; c < 512; c += 256) {
            const int r = c >> 2, sg = c & 3;
            const uint32_t d = sb + r * (AST * 2) + sg * 16;
            const size_t ga = (size_t)(row0 + r) * lda + k0 + sg * 8;
            const size_t gb = (size_t)(col0 + r) * ldb + k0 + sg * 8;
            cpa16(d,             Ah + ga);
            cpa16(d + TILEB,     Al + ga);
            cpa16(d + 2 * TILEB, Bh + gb);
            cpa16(d + 3 * TILEB, Bl + gb);
        }
    };

    load_tile(0); cp_commit();
    load_tile(1); cp_commit();

    for (int i = 0; i < nk; i++) {
        // prefetch chunk i+2 into stage (i+2)%3 (chunk i-1's stage, freed by
        // the trailing __syncthreads of iteration i-1)
        if (i + 2 < nk) { load_tile(i + 2); cp_commit(); cp_wait2(); }
        else if (i + 1 < nk) cp_wait1();
        else cp_wait0();
        __syncthreads();   // all threads' chunk-i copies complete AND visible

        const uint32_t sb = smb + (i % NSTAGE) * STAGEB;
#pragma unroll
        for (int ks = 0; ks < 2; ks++) {
            uint32_t ah[4][4], al[4][4], bh[4][2], bl[4][2];
            const int acol = ks * 32 + ((lane >> 4) & 1) * 16;   // bytes
#pragma unroll
            for (int mt = 0; mt < 4; mt++) {
                const int row = wm * 64 + mt * 16 + ((lane >> 3) & 1) * 8 + (lane & 7);
                const uint32_t a = sb + row * (AST * 2) + acol;
                ldm4(ah[mt], a);
                ldm4(al[mt], a + TILEB);
            }
            const int bcol = ks * 32 + ((lane >> 3) & 1) * 16;   // bytes
#pragma unroll
            for (int p = 0; p < 2; p++) {
                const int row = wn * 32 + p * 16 + ((lane >> 4) & 1) * 8 + (lane & 7);
                const uint32_t a = sb + 2 * TILEB + row * (AST * 2) + bcol;
                uint32_t r[4];
                ldm4(r, a);
                bh[2*p][0] = r[0]; bh[2*p][1] = r[1];
                bh[2*p+1][0] = r[2]; bh[2*p+1][1] = r[3];
                ldm4(r, a + TILEB);
                bl[2*p][0] = r[0]; bl[2*p][1] = r[1];
                bl[2*p+1][0] = r[2]; bl[2*p+1][1] = r[3];
            }
#pragma unroll
            for (int mt = 0; mt < 4; mt++)
#pragma unroll
                for (int nt = 0; nt < 4; nt++) {
                    mma16816(acc[mt][nt], ah[mt], bh[nt]);
                    mma16816(acc[mt][nt], ah[mt], bl[nt]);
                    mma16816(acc[mt][nt], al[mt], bh[nt]);
                }
        }
        __syncthreads();   // all warps done reading stage i%3 before it is reloaded
    }

    // ---- epilogue ----
#pragma unroll
    for (int mt = 0; mt < 4; mt++) {
#pragma unroll
        for (int nt = 0; nt < 4; nt++) {
            const int row = row0 + wm * 64 + mt * 16 + (lane >> 2);
            const int col = col0 + wn * 32 + nt * 8 + (lane & 3) * 2;
            float v0 = acc[mt][nt][0] * alpha;
            float v1 = acc[mt][nt][1] * alpha;
            float v2 = acc[mt][nt][2] * alpha;
            float v3 = acc[mt][nt][3] * alpha;
            const long long o0 = z * sC + (long long)row * ldc + col;
            const long long o1 = o0 + 8LL * ldc;
            if (OUTF32) {
                if (bias) {
                    float b0 = __ldg(bias + col), b1 = __ldg(bias + col + 1);
                    v0 += b0; v1 += b1; v2 += b0; v3 += b1;
                }
                if (Res) {
                    float2 r0 = *reinterpret_cast<const float2*>(Res + o0);
                    float2 r1 = *reinterpret_cast<const float2*>(Res + o1);
                    v0 += r0.x; v1 += r0.y; v2 += r1.x; v3 += r1.y;
                }
                *reinterpret_cast<float2*>(Cf + o0) = make_float2(v0, v1);
                *reinterpret_cast<float2*>(Cf + o1) = make_float2(v2, v3);
            } else {
                bf16 h0,l0,h1,l1,h2,l2,h3,l3;
                split_bf16(v0,h0,l0); split_bf16(v1,h1,l1);
                split_bf16(v2,h2,l2); split_bf16(v3,h3,l3);
                __nv_bfloat162 hh0(h0,h1), hh1(h2,h3), ll0(l0,l1), ll1(l2,l3);
                *reinterpret_cast<uint32_t*>(Chi + o0) = *reinterpret_cast<uint32_t*>(&hh0);
                *reinterpret_cast<uint32_t*>(Chi + o1) = *reinterpret_cast<uint32_t*>(&hh1);
                *reinterpret_cast<uint32_t*>(Clo + o0) = *reinterpret_cast<uint32_t*>(&ll0);
                *reinterpret_cast<uint32_t*>(Clo + o1) = *reinterpret_cast<uint32_t*>(&ll1);
            }
        }
    }
}

// ---------------- weight transpose + split (vectorized): in[K,N] fp32 -> out[N,K] bf16 hi/lo ----
// Tile: 32 K-rows x 128 N-cols. float4 loads, 16-bf16 packed stores, conflict-free smem.
struct __align__(16) B8 { bf16 v[8]; };

__global__ void __launch_bounds__(256)
convT_kernel(const float* __restrict__ in, bf16* __restrict__ hi, bf16* __restrict__ lo,
             int K, int N)
{
    __shared__ float s[32][129];
    const int n0 = blockIdx.x * 128, k0 = blockIdx.y * 32;
    const int t = threadIdx.x;
    const int r = t >> 5, c4 = (t & 31) * 4;
#pragma unroll
    for (int rr = 0; rr < 4; rr++) {
        const int k = r + rr * 8;
        float4 v = *reinterpret_cast<const float4*>(in + (size_t)(k0 + k) * N + n0 + c4);
        s[k][c4] = v.x; s[k][c4+1] = v.y; s[k][c4+2] = v.z; s[k][c4+3] = v.w;
    }
    __syncthreads();
    const int n = t >> 1, kk0 = (t & 1) * 16;
    B8 hb[2], lb[2];
#pragma unroll
    for (int kk = 0; kk < 16; kk++) {
        bf16 h, l;
        split_bf16(s[kk0 + kk][n], h, l);
        hb[kk >> 3].v[kk & 7] = h;
        lb[kk >> 3].v[kk & 7] = l;
    }
    const size_t o = (size_t)(n0 + n) * K + k0 + kk0;
    *reinterpret_cast<B8*>(hi + o)     = hb[0];
    *reinterpret_cast<B8*>(hi + o + 8) = hb[1];
    *reinterpret_cast<B8*>(lo + o)     = lb[0];
    *reinterpret_cast<B8*>(lo + o + 8) = lb[1];
}

// ---------------- pack QKV biases into one 2560-vector ----------------
__global__ void packbias_kernel(const float* __restrict__ bq, const float* __restrict__ bk,
                                const float* __restrict__ bv, float* __restrict__ o)
{
    int i = blockIdx.x * 256 + threadIdx.x;
    if (i < 2048) o[i] = bq[i];
    else if (i < 2304) o[i] = bk[i - 2048];
    else if (i < 2560) o[i] = bv[i - 2304];
}

// ---------------- RMSNorm: MODE 0 -> fp32 out, MODE 1 -> bf16 hi/lo ----------------
template<int MODE>
__global__ void __launch_bounds__(256)
rmsnorm_kernel(const float* __restrict__ x, const float* __restrict__ w,
               float* __restrict__ yf, bf16* __restrict__ yh, bf16* __restrict__ yl)
{
    int s = blockIdx.x;
    const float* row = x + (size_t)s * Hn;
    float4 buf[2];
    float ss = 0.f;
#pragma unroll
    for (int it = 0; it < 2; it++) {
        int j = (it * 256 + threadIdx.x) * 4;
        float4 v = *reinterpret_cast<const float4*>(row + j);
        buf[it] = v;
        ss += v.x * v.x + v.y * v.y + v.z * v.z + v.w * v.w;
    }
    ss = blockSum256(ss);
    float inv = rsqrtf(ss * (1.0f / Hn) + EPSn);
#pragma unroll
    for (int it = 0; it < 2; it++) {
        int j = (it * 256 + threadIdx.x) * 4;
        float4 wv = *reinterpret_cast<const float4*>(w + j);
        float o0 = buf[it].x * inv * wv.x;
        float o1 = buf[it].y * inv * wv.y;
        float o2 = buf[it].z * inv * wv.z;
        float o3 = buf[it].w * inv * wv.w;
        if (MODE == 0) {
            *reinterpret_cast<float4*>(yf + (size_t)s * Hn + j) = make_float4(o0, o1, o2, o3);
        } else {
            bf16 h0,l0,h1,l1,h2,l2,h3,l3;
            split_bf16(o0,h0,l0); split_bf16(o1,h1,l1);
            split_bf16(o2,h2,l2); split_bf16(o3,h3,l3);
            __nv_bfloat162 hh0(h0,h1), hh1(h2,h3), ll0(l0,l1), ll1(l2,l3);
            uint2 uh = make_uint2(*reinterpret_cast<uint32_t*>(&hh0), *reinterpret_cast<uint32_t*>(&hh1));
            uint2 ul = make_uint2(*reinterpret_cast<uint32_t*>(&ll0), *reinterpret_cast<uint32_t*>(&ll1));
            *reinterpret_cast<uint2*>(yh + (size_t)s * Hn + j) = uh;
            *reinterpret_cast<uint2*>(yl + (size_t)s * Hn + j) = ul;
        }
    }
}

// ---------------- RoPE for Q: fp32 (strided in qkv) -> bf16 hi/lo dense [S,2048] ----------------
__global__ void rope_q_kernel(const float* __restrict__ qkv, const int* __restrict__ pos,
                              bf16* __restrict__ qh, bf16* __restrict__ ql)
{
    int s = blockIdx.x, h = blockIdx.y, d = threadIdx.x; // d in [0,64)
    double ang = (double)pos[s] * exp(-(double)d / 64.0 * 13.815510557964274);
    double sd, cd; sincos(ang, &sd, &cd);
    float c = (float)cd, sn = (float)sd;
    size_t ibase = (size_t)s * 2560 + h * HDn;
    size_t obase = ((size_t)s * NHn + h) * HDn;
    float x1 = qkv[ibase + d], x2 = qkv[ibase + d + 64];
    float v1 = x1 * c - x2 * sn;
    float v2 = x2 * c + x1 * sn;
    bf16 hh, ll;
    split_bf16(v1, hh, ll); qh[obase + d] = hh;      ql[obase + d] = ll;
    split_bf16(v2, hh, ll); qh[obase + d + 64] = hh; ql[obase + d + 64] = ll;
}

// ---------------- K/V cache: fp32 caches (to d_out) + bf16 hi/lo K + transposed V ----------------
__global__ void kv_cache_kernel(const float* __restrict__ qkv,
                                const float* __restrict__ pastk, const float* __restrict__ pastv,
                                const int* __restrict__ pos,
                                float* __restrict__ kc, float* __restrict__ vc,
                                bf16* __restrict__ kh, bf16* __restrict__ kl,
                                bf16* __restrict__ vth, bf16* __restrict__ vtl)
{
    int t = blockIdx.x, kv = blockIdx.y, d = threadIdx.x; // d in [0,128)
    size_t oidx = ((size_t)kv * Tn + t) * HDn + d;
    float kval, vval;
    if (t < Pn) {
        size_t pidx = ((size_t)kv * Pn + t) * HDn + d;
        kval = pastk[pidx];
        vval = pastv[pidx];
    } else {
        int s = t - Pn;
        const float* kr = qkv + (size_t)s * 2560 + 2048 + kv * HDn;
        int dr = d & 63;
        double ang = (double)pos[s] * exp(-(double)dr / 64.0 * 13.815510557964274);
        double sd, cd; sincos(ang, &sd, &cd);
        float c = (float)cd, sn = (float)sd;
        if (d < 64) kval = kr[d] * c - kr[d + 64] * sn;
        else        kval = kr[d] * c + kr[d - 64] * sn;
        vval = qkv[(size_t)s * 2560 + 2304 + kv * HDn + d];
    }
    kc[oidx] = kval;
    vc[oidx] = vval;
    bf16 h, l;
    split_bf16(kval, h, l); kh[oidx] = h; kl[oidx] = l;
    split_bf16(vval, h, l);
    size_t tidx = ((size_t)kv * HDn + d) * Tn + t;
    vth[tidx] = h; vtl[tidx] = l;
}

// ---------------- masked softmax: fp32 scores -> bf16 hi/lo P ----------------
__global__ void __launch_bounds__(256)
softmax_kernel(const float* __restrict__ scores, const int* __restrict__ pos,
               bf16* __restrict__ ph, bf16* __restrict__ pl)
{
    int s = blockIdx.x, h = blockIdx.y;
    size_t rbase = ((size_t)h * Sn + s) * Tn;
    const float* row = scores + rbase;
    int lim = pos[s];
    int tid = threadIdx.x;
    float v[8];
    float m = -1e30f;
#pragma unroll
    for (int it = 0; it < 2; it++) {
        int t0 = (it * 256 + tid) * 4;
        float4 x = *reinterpret_cast<const float4*>(row + t0);
        float xs[4] = {x.x, x.y, x.z, x.w};
#pragma unroll
        for (int e = 0; e < 4; e++) {
            float val = (t0 + e <= lim) ? xs[e] : -1e30f;
            v[it * 4 + e] = val;
            m = fmaxf(m, val);
        }
    }
    m = blockMax256(m);
    float sum = 0.f;
#pragma unroll
    for (int e = 0; e < 8; e++) {
        float ex = (v[e] > -1e29f) ? expf(v[e] - m) : 0.f;
        v[e] = ex;
        sum += ex;
    }
    sum = blockSum256(sum);
    float inv = 1.f / sum;
#pragma unroll
    for (int it = 0; it < 2; it++) {
        int t0 = (it * 256 + tid) * 4;
        bf16 h0,l0,h1,l1,h2,l2,h3,l3;
        split_bf16(v[it*4+0] * inv, h0, l0);
        split_bf16(v[it*4+1] * inv, h1, l1);
        split_bf16(v[it*4+2] * inv, h2, l2);
        split_bf16(v[it*4+3] * inv, h3, l3);
        __nv_bfloat162 hh0(h0,h1), hh1(h2,h3), ll0(l0,l1), ll1(l2,l3);
        uint2 uh = make_uint2(*reinterpret_cast<uint32_t*>(&hh0), *reinterpret_cast<uint32_t*>(&hh1));
        uint2 ul = make_uint2(*reinterpret_cast<uint32_t*>(&ll0), *reinterpret_cast<uint32_t*>(&ll1));
        *reinterpret_cast<uint2*>(ph + rbase + t0) = uh;
        *reinterpret_cast<uint2*>(pl + rbase + t0) = ul;
    }
}

// ---------------- SiLU(gate) * up -> bf16 hi/lo (reads fused [S,11264] buffer) ----------------
__global__ void silu_mul_kernel(const float* __restrict__ gu,
                                bf16* __restrict__ oh, bf16* __restrict__ ol, int n4)
{
    int i = blockIdx.x * blockDim.x + threadIdx.x;
    if (i < n4) {
        const int m = i / (FFn / 4);
        const int j = (i - m * (FFn / 4)) * 4;
        const size_t gbase = (size_t)m * (2 * FFn);
        float4 gv = *reinterpret_cast<const float4*>(gu + gbase + j);
        float4 uv = *reinterpret_cast<const float4*>(gu + gbase + FFn + j);
        float r0 = gv.x / (1.f + expf(-gv.x)) * uv.x;
        float r1 = gv.y / (1.f + expf(-gv.y)) * uv.y;
        float r2 = gv.z / (1.f + expf(-gv.z)) * uv.z;
        float r3 = gv.w / (1.f + expf(-gv.w)) * uv.w;
        bf16 h0,l0,h1,l1,h2,l2,h3,l3;
        split_bf16(r0,h0,l0); split_bf16(r1,h1,l1);
        split_bf16(r2,h2,l2); split_bf16(r3,h3,l3);
        __nv_bfloat162 hh0(h0,h1), hh1(h2,h3), ll0(l0,l1), ll1(l2,l3);
        uint2 uh = make_uint2(*reinterpret_cast<uint32_t*>(&hh0), *reinterpret_cast<uint32_t*>(&hh1));
        uint2 ul = make_uint2(*reinterpret_cast<uint32_t*>(&ll0), *reinterpret_cast<uint32_t*>(&ll1));
        *reinterpret_cast<uint2*>(oh + (size_t)m * FFn + j) = uh;
        *reinterpret_cast<uint2*>(ol + (size_t)m * FFn + j) = ul;
    }
}

// ---------------- host-side launch helper ----------------
template<int OUTF32, int CAUSAL>
static void mmagemm(const bf16* Ah, const bf16* Al, const bf16* Bh, const bf16* Bl,
                    const float* bias, const float* Res,
                    float* Cf, bf16* Chi, bf16* Clo,
                    int M, int N, int K, int lda, int ldb, int ldc,
                    long long sA, long long sB, long long sC, int bdiv, float alpha, int batch)
{
    dim3 grid(N / 128, M / 128, batch);
    mma_gemm<OUTF32, CAUSAL><<<grid, 256, NSTAGE * STAGEB>>>(
        Ah, Al, Bh, Bl, bias, Res, Cf, Chi, Clo,
        K, lda, ldb, ldc, sA, sB, sC, bdiv, alpha);
}

extern "C" void kernel_launch(void* const* d_in, const int* in_sizes, int n_in,
                              void* d_out, int out_size)
{
    (void)in_sizes; (void)n_in; (void)out_size;
    const float* embeds = (const float*)d_in[0];
    const int*   pos    = (const int*)  d_in[1];
    const float* past_k = (const float*)d_in[2];
    const float* past_v = (const float*)d_in[3];
    const float* ln1    = (const float*)d_in[4];
    const float* wq     = (const float*)d_in[5];
    const float* bq     = (const float*)d_in[6];
    const float* wk     = (const float*)d_in[7];
    const float* bk     = (const float*)d_in[8];
    const float* wv     = (const float*)d_in[9];
    const float* bv     = (const float*)d_in[10];
    const float* wo     = (const float*)d_in[11];
    const float* ln2    = (const float*)d_in[12];
    const float* wg     = (const float*)d_in[13];
    const float* wu     = (const float*)d_in[14];
    const float* wd     = (const float*)d_in[15];
    const float* normw  = (const float*)d_in[16];
    float* out = (float*)d_out;

    cudaFuncSetAttribute(mma_gemm<1,0>, cudaFuncAttributeMaxDynamicSharedMemorySize, NSTAGE * STAGEB);
    cudaFuncSetAttribute(mma_gemm<1,1>, cudaFuncAttributeMaxDynamicSharedMemorySize, NSTAGE * STAGEB);
    cudaFuncSetAttribute(mma_gemm<0,2>, cudaFuncAttributeMaxDynamicSharedMemorySize, NSTAGE * STAGEB);

    float *hid, *qkv, *sc, *gu, *bqkv;
    cudaGetSymbolAddress((void**)&hid,  g_hid);
    cudaGetSymbolAddress((void**)&qkv,  g_qkv);
    cudaGetSymbolAddress((void**)&sc,   g_scores);
    cudaGetSymbolAddress((void**)&gu,   g_gateup);
    cudaGetSymbolAddress((void**)&bqkv, g_bqkv);
    bf16 *hnh,*hnl,*qh,*ql,*kh,*kl,*vth,*vtl,*ph,*pl,*ath,*atl,*gh,*gl,*wh,*wl;
    cudaGetSymbolAddress((void**)&hnh, g_hn_hi); cudaGetSymbolAddress((void**)&hnl, g_hn_lo);
    cudaGetSymbolAddress((void**)&qh,  g_q_hi);  cudaGetSymbolAddress((void**)&ql,  g_q_lo);
    cudaGetSymbolAddress((void**)&kh,  g_k_hi);  cudaGetSymbolAddress((void**)&kl,  g_k_lo);
    cudaGetSymbolAddress((void**)&vth, g_vt_hi); cudaGetSymbolAddress((void**)&vtl, g_vt_lo);
    cudaGetSymbolAddress((void**)&ph,  g_p_hi);  cudaGetSymbolAddress((void**)&pl,  g_p_lo);
    cudaGetSymbolAddress((void**)&ath, g_at_hi); cudaGetSymbolAddress((void**)&atl, g_at_lo);
    cudaGetSymbolAddress((void**)&gh,  g_g_hi);  cudaGetSymbolAddress((void**)&gl,  g_g_lo);
    cudaGetSymbolAddress((void**)&wh,  g_w_hi);  cudaGetSymbolAddress((void**)&wl,  g_w_lo);

    // per-layer offsets into transposed weight store (QKV and G|U are contiguous)
    const long long OQ = 0, OO = 5242880, OG = 9437184, OD = 32505856;
    const long long OK_ = 4194304, OV = 4718592, OU = 20971520;

    // ---- transpose + split all weights (vectorized) ----
    dim3 cb(256);
    for (int l = 0; l < Ln; l++) {
        long long base = (long long)l * WL;
        convT_kernel<<<dim3(2048/128, 2048/32), cb>>>(wq + (size_t)l*Hn*2048, wh + base + OQ,  wl + base + OQ,  Hn, 2048);
        convT_kernel<<<dim3(256/128,  2048/32), cb>>>(wk + (size_t)l*Hn*256,  wh + base + OK_, wl + base + OK_, Hn, 256);
        convT_kernel<<<dim3(256/128,  2048/32), cb>>>(wv + (size_t)l*Hn*256,  wh + base + OV,  wl + base + OV,  Hn, 256);
        convT_kernel<<<dim3(2048/128, 2048/32), cb>>>(wo + (size_t)l*Hn*Hn,   wh + base + OO,  wl + base + OO,  Hn, 2048);
        convT_kernel<<<dim3(5632/128, 2048/32), cb>>>(wg + (size_t)l*Hn*FFn,  wh + base + OG,  wl + base + OG,  Hn, FFn);
        convT_kernel<<<dim3(5632/128, 2048/32), cb>>>(wu + (size_t)l*Hn*FFn,  wh + base + OU,  wl + base + OU,  Hn, FFn);
        convT_kernel<<<dim3(2048/128, 5632/32), cb>>>(wd + (size_t)l*FFn*Hn,  wh + base + OD,  wl + base + OD,  FFn, 2048);
    }

    cudaMemcpyAsync(hid, embeds, sizeof(float) * Sn * Hn, cudaMemcpyDeviceToDevice);

    for (int l = 0; l < Ln; l++) {
        long long base = (long long)l * WL;
        float* kc = out + (size_t)Sn * Hn + (size_t)l * 2 * NKVn * Tn * HDn;
        float* vc = kc + (size_t)NKVn * Tn * HDn;

        // pre-attention norm -> bf16 hi/lo
        rmsnorm_kernel<1><<<Sn, 256>>>(hid, ln1 + (size_t)l * Hn, nullptr, hnh, hnl);

        // fused QKV projection (N=2560) -> fp32 qkv buffer
        packbias_kernel<<<10, 256>>>(bq + (size_t)l*2048, bk + (size_t)l*256, bv + (size_t)l*256, bqkv);
        mmagemm<1,0>(hnh, hnl, wh + base + OQ, wl + base + OQ, bqkv, nullptr,
                     qkv, nullptr, nullptr, Sn, 2560, Hn, Hn, Hn, 2560, 0, 0, 0, 1, 1.f, 1);

        // RoPE Q -> bf16 hi/lo; KV cache (fp32 to d_out + bf16 hi/lo, V transposed)
        rope_q_kernel<<<dim3(Sn, NHn), 64>>>(qkv, pos, qh, ql);
        kv_cache_kernel<<<dim3(Tn, NKVn), HDn>>>(
            qkv,
            past_k + (size_t)l * NKVn * Pn * HDn,
            past_v + (size_t)l * NKVn * Pn * HDn,
            pos, kc, vc, kh, kl, vth, vtl);

        // scores[h] = SCALE * Q_h @ K_{h/G}^T   (fp32 out, fully-masked tiles skipped)
        mmagemm<1,1>(qh, ql, kh, kl, nullptr, nullptr, sc, nullptr, nullptr,
                     Sn, Tn, HDn, NHn*HDn, HDn, Tn,
                     (long long)HDn, (long long)Tn*HDn, (long long)Sn*Tn, Gn, SCALEn, NHn);

        softmax_kernel<<<dim3(Sn, NHn), 256>>>(sc, pos, ph, pl);

        // attn_out[h] = P_h @ V_{h/G}  (K clipped to valid keys), bf16 hi/lo out
        mmagemm<0,2>(ph, pl, vth, vtl, nullptr, nullptr, nullptr, ath, atl,
                     Sn, HDn, Tn, Tn, Tn, NHn*HDn,
                     (long long)Sn*Tn, (long long)HDn*Tn, (long long)HDn, Gn, 1.f, NHn);

        // output projection + residual (fp32)
        mmagemm<1,0>(ath, atl, wh + base + OO, wl + base + OO, nullptr, hid,
                     hid, nullptr, nullptr, Sn, Hn, Hn, Hn, Hn, Hn, 0, 0, 0, 1, 1.f, 1);

        // MLP: fused gate|up GEMM (N=11264) -> silu*mul -> down
        rmsnorm_kernel<1><<<Sn, 256>>>(hid, ln2 + (size_t)l * Hn, nullptr, hnh, hnl);
        mmagemm<1,0>(hnh, hnl, wh + base + OG, wl + base + OG, nullptr, nullptr,
                     gu, nullptr, nullptr, Sn, 2*FFn, Hn, Hn, Hn, 2*FFn, 0, 0, 0, 1, 1.f, 1);
        silu_mul_kernel<<<(Sn * FFn / 4 + 255) / 256, 256>>>(gu, gh, gl, Sn * FFn / 4);
        mmagemm<1,0>(gh, gl, wh + base + OD, wl + base + OD, nullptr, hid,
                     hid, nullptr, nullptr, Sn, Hn, FFn, FFn, FFn, Hn, 0, 0, 0, 1, 1.f, 1);
    }

    // final norm -> fp32 hidden output
    rmsnorm_kernel<0><<<Sn, 256>>>(hid, normw, out, nullptr, nullptr);
}

// round 9
// speedup vs baseline: 3.2962x; 1.0498x over previous
#include <cuda_runtime.h>
#include <cuda_bf16.h>
#include <math.h>
#include <stdint.h>

// ---------------- problem constants ----------------
#define Ln   2
#define Hn   2048
#define NHn  16
#define NKVn 2
#define HDn  128
#define Sn   1024
#define Pn   1024
#define FFn  5632
#define Tn   (Pn + Sn)       // 2048
#define Gn   (NHn / NKVn)    // 8
#define EPSn 1e-6f
#define SCALEn 0.08838834764831845f  // 1/sqrt(128)

typedef __nv_bfloat16 bf16;

// ---------------- device scratch (static, no allocation) ----------------
static __device__ float g_hid   [Sn * Hn];
static __device__ float g_qkv   [Sn * 2560];
static __device__ float g_gateup[(size_t)Sn * (2 * FFn)];     // 46 MB
static __device__ float g_bqkv  [2560];

static __device__ bf16 g_hn_hi[Sn * Hn],  g_hn_lo[Sn * Hn];
static __device__ bf16 g_q_hi [Sn * Hn],  g_q_lo [Sn * Hn];
static __device__ bf16 g_k_hi [NKVn * Tn * HDn], g_k_lo [NKVn * Tn * HDn];
static __device__ bf16 g_vt_hi[NKVn * HDn * Tn], g_vt_lo[NKVn * HDn * Tn];
static __device__ bf16 g_at_hi[Sn * Hn],  g_at_lo[Sn * Hn];
static __device__ bf16 g_g_hi [(size_t)Sn * FFn], g_g_lo [(size_t)Sn * FFn];

// transposed+split weights: per layer [wq(2048x2048), wk(256x2048), wv(256x2048),
//  wo(2048x2048), wg(5632x2048), wu(5632x2048), wd(2048x5632)]  (all [N,K])
#define WL 44040192LL
#define WTOT (2 * WL)
static __device__ bf16 g_w_hi[WTOT], g_w_lo[WTOT];

// ---------------- small helpers ----------------
__device__ __forceinline__ float warpSum(float v) {
#pragma unroll
    for (int o = 16; o; o >>= 1) v += __shfl_xor_sync(0xffffffffu, v, o);
    return v;
}
__device__ float blockSum256(float v) {
    __shared__ float sm[8]; __shared__ float res;
    v = warpSum(v);
    if ((threadIdx.x & 31) == 0) sm[threadIdx.x >> 5] = v;
    __syncthreads();
    float w = (threadIdx.x < 8) ? sm[threadIdx.x] : 0.f;
    w = warpSum(w);
    if (threadIdx.x == 0) res = w;
    __syncthreads();
    return res;
}

__device__ __forceinline__ void split_bf16(float x, bf16& h, bf16& l) {
    h = __float2bfloat16(x);
    l = __float2bfloat16(x - __bfloat162float(h));
}
__device__ __forceinline__ uint32_t b2u(__nv_bfloat162 v) {
    return *reinterpret_cast<uint32_t*>(&v);
}

// ---------------- PTX wrappers (plain sm_80+ features only) ----------------
__device__ __forceinline__ uint32_t smem_u32(const void* p) {
    uint32_t a;
    asm("{ .reg .u64 t; cvta.to.shared.u64 t, %1; cvt.u32.u64 %0, t; }" : "=r"(a) : "l"(p));
    return a;
}
__device__ __forceinline__ void cpa16(uint32_t d, const void* s) {
    asm volatile("cp.async.cg.shared.global [%0], [%1], 16;" :: "r"(d), "l"(s));
}
__device__ __forceinline__ void cp_commit() {
    asm volatile("cp.async.commit_group;" ::: "memory");
}
__device__ __forceinline__ void cp_wait2() {
    asm volatile("cp.async.wait_group 2;" ::: "memory");
}
__device__ __forceinline__ void cp_wait1() {
    asm volatile("cp.async.wait_group 1;" ::: "memory");
}
__device__ __forceinline__ void cp_wait0() {
    asm volatile("cp.async.wait_group 0;" ::: "memory");
}
__device__ __forceinline__ void ldm4(uint32_t* r, uint32_t a) {
    asm volatile("ldmatrix.sync.aligned.m8n8.x4.shared.b16 {%0,%1,%2,%3}, [%4];"
        : "=r"(r[0]), "=r"(r[1]), "=r"(r[2]), "=r"(r[3]) : "r"(a));
}
__device__ __forceinline__ void mma16816(float* c, const uint32_t* a, const uint32_t* b) {
    asm volatile(
        "mma.sync.aligned.m16n8k16.row.col.f32.bf16.bf16.f32 "
        "{%0,%1,%2,%3}, {%4,%5,%6,%7}, {%8,%9}, {%0,%1,%2,%3};"
        : "+f"(c[0]), "+f"(c[1]), "+f"(c[2]), "+f"(c[3])
        : "r"(a[0]), "r"(a[1]), "r"(a[2]), "r"(a[3]), "r"(b[0]), "r"(b[1]));
}

// ---------------- tensor-core GEMM (mma.sync bf16, 3-way split, 3-stage pipe) ----------------
// C[M,N] = alpha * A[M,K] @ B[N,K]^T (+bias)(+Res). A/B are bf16 hi/lo pairs.
#define AST  40                        // smem row stride in bf16 (80 B)
#define TILEB (128 * AST * 2)          // 10240 B per plane
#define STAGEB (4 * TILEB)             // Ah, Al, Bh, Bl
#define NSTAGE 3

__global__ void __launch_bounds__(256, 1)
mma_gemm(const bf16* __restrict__ Ah, const bf16* __restrict__ Al,
         const bf16* __restrict__ Bh, const bf16* __restrict__ Bl,
         const float* __restrict__ bias, const float* __restrict__ Res,
         float* __restrict__ Cf,
         int K, int lda, int ldb, int ldc)
{
    extern __shared__ char smc[];
    const int tid = threadIdx.x;
    const int lane = tid & 31;
    const int wid = tid >> 5;
    const int wm = wid >> 2;           // 0..1
    const int wn = wid & 3;            // 0..3
    const int row0 = blockIdx.y * 128;
    const int col0 = blockIdx.x * 128;

    const uint32_t smb = smem_u32(smc);

    float acc[4][4][4];
#pragma unroll
    for (int i = 0; i < 4; i++)
#pragma unroll
        for (int j = 0; j < 4; j++)
#pragma unroll
            for (int e = 0; e < 4; e++) acc[i][j][e] = 0.f;

    const int nk = K >> 5;

    auto load_tile = [&](int i) {
        const int k0 = i << 5;
        const uint32_t sb = smb + (i % NSTAGE) * STAGEB;
#pragma unroll
        for (int c = tid; c < 512; c += 256) {
            const int r = c >> 2, sg = c & 3;
            const uint32_t d = sb + r * (AST * 2) + sg * 16;
            const size_t ga = (size_t)(row0 + r) * lda + k0 + sg * 8;
            const size_t gb = (size_t)(col0 + r) * ldb + k0 + sg * 8;
            cpa16(d,             Ah + ga);
            cpa16(d + TILEB,     Al + ga);
            cpa16(d + 2 * TILEB, Bh + gb);
            cpa16(d + 3 * TILEB, Bl + gb);
        }
    };

    load_tile(0); cp_commit();
    load_tile(1); cp_commit();

    for (int i = 0; i < nk; i++) {
        if (i + 2 < nk) { load_tile(i + 2); cp_commit(); cp_wait2(); }
        else if (i + 1 < nk) cp_wait1();
        else cp_wait0();
        __syncthreads();

        const uint32_t sb = smb + (i % NSTAGE) * STAGEB;
#pragma unroll
        for (int ks = 0; ks < 2; ks++) {
            uint32_t ah[4][4], al[4][4], bh[4][2], bl[4][2];
            const int acol = ks * 32 + ((lane >> 4) & 1) * 16;
#pragma unroll
            for (int mt = 0; mt < 4; mt++) {
                const int row = wm * 64 + mt * 16 + ((lane >> 3) & 1) * 8 + (lane & 7);
                const uint32_t a = sb + row * (AST * 2) + acol;
                ldm4(ah[mt], a);
                ldm4(al[mt], a + TILEB);
            }
            const int bcol = ks * 32 + ((lane >> 3) & 1) * 16;
#pragma unroll
            for (int p = 0; p < 2; p++) {
                const int row = wn * 32 + p * 16 + ((lane >> 4) & 1) * 8 + (lane & 7);
                const uint32_t a = sb + 2 * TILEB + row * (AST * 2) + bcol;
                uint32_t r[4];
                ldm4(r, a);
                bh[2*p][0] = r[0]; bh[2*p][1] = r[1];
                bh[2*p+1][0] = r[2]; bh[2*p+1][1] = r[3];
                ldm4(r, a + TILEB);
                bl[2*p][0] = r[0]; bl[2*p][1] = r[1];
                bl[2*p+1][0] = r[2]; bl[2*p+1][1] = r[3];
            }
#pragma unroll
            for (int mt = 0; mt < 4; mt++)
#pragma unroll
                for (int nt = 0; nt < 4; nt++) {
                    mma16816(acc[mt][nt], ah[mt], bh[nt]);
                    mma16816(acc[mt][nt], ah[mt], bl[nt]);
                    mma16816(acc[mt][nt], al[mt], bh[nt]);
                }
        }
        __syncthreads();
    }

#pragma unroll
    for (int mt = 0; mt < 4; mt++) {
#pragma unroll
        for (int nt = 0; nt < 4; nt++) {
            const int row = row0 + wm * 64 + mt * 16 + (lane >> 2);
            const int col = col0 + wn * 32 + nt * 8 + (lane & 3) * 2;
            float v0 = acc[mt][nt][0];
            float v1 = acc[mt][nt][1];
            float v2 = acc[mt][nt][2];
            float v3 = acc[mt][nt][3];
            const long long o0 = (long long)row * ldc + col;
            const long long o1 = o0 + 8LL * ldc;
            if (bias) {
                float b0 = __ldg(bias + col), b1 = __ldg(bias + col + 1);
                v0 += b0; v1 += b1; v2 += b0; v3 += b1;
            }
            if (Res) {
                float2 r0 = *reinterpret_cast<const float2*>(Res + o0);
                float2 r1 = *reinterpret_cast<const float2*>(Res + o1);
                v0 += r0.x; v1 += r0.y; v2 += r1.x; v3 += r1.y;
            }
            *reinterpret_cast<float2*>(Cf + o0) = make_float2(v0, v1);
            *reinterpret_cast<float2*>(Cf + o1) = make_float2(v2, v3);
        }
    }
}

// ---------------- flash attention (fused QK^T -> softmax -> PV) ----------------
// CTA = 1 head x 128 q rows (8 warps x 16 rows). Key tiles of 64, 2-stage cp.async.
// Q resident in SMEM; K tile [key][hd] (B operand of S); V tile [hd][key] (B operand of O).
// 3-way bf16 split on both matmuls. Online softmax in registers. Output: bf16 hi/lo.
#define TkF   64
#define QSTRB 272                   // Q/K smem row stride bytes (136 bf16)
#define VSTRB 144                   // V smem row stride bytes (72 bf16)
#define QPL   (128 * QSTRB)         // 34816 per plane
#define KPL   (64 * QSTRB)          // 17408 per plane
#define VPL   (128 * VSTRB)         // 18432 per plane
#define FSTG  (2 * KPL + 2 * VPL)   // 71680 per stage
#define FKOFF (2 * QPL)             // 69632
#define FSMEM (FKOFF + 2 * FSTG)    // 212992

__global__ void __launch_bounds__(256, 1)
flash_kernel(const bf16* __restrict__ qhp, const bf16* __restrict__ qlp,
             const bf16* __restrict__ khp, const bf16* __restrict__ klp,
             const bf16* __restrict__ vthp, const bf16* __restrict__ vtlp,
             bf16* __restrict__ ohp, bf16* __restrict__ olp)
{
    extern __shared__ char smc[];
    const uint32_t smb = smem_u32(smc);
    const int tid = threadIdx.x, lane = tid & 31, wid = tid >> 5;
    const int qb = blockIdx.x, h = blockIdx.y;
    const int row0 = qb * 128;
    const int kvh = h >> 3;
    const int nkt = 18 + 2 * qb;        // (Pn + row0 + 128) / TkF

    // Q tile: 128 rows x 128 cols, both planes
    for (int c = tid; c < 2048; c += 256) {
        const int r = c >> 4, sg = c & 15;
        const uint32_t d = smb + r * QSTRB + sg * 16;
        const size_t src = (size_t)(row0 + r) * Hn + h * HDn + sg * 8;
        cpa16(d, qhp + src);
        cpa16(d + QPL, qlp + src);
    }
    cp_commit();

    auto load_kv = [&](int kt) {
        const int t0 = kt * TkF;
        const uint32_t base = smb + FKOFF + (kt & 1) * FSTG;
        for (int c = tid; c < 1024; c += 256) {
            const int r = c >> 4, sg = c & 15;
            const uint32_t d = base + r * QSTRB + sg * 16;
            const size_t src = ((size_t)kvh * Tn + t0 + r) * HDn + sg * 8;
            cpa16(d, khp + src);
            cpa16(d + KPL, klp + src);
        }
        for (int c = tid; c < 1024; c += 256) {
            const int r = c >> 3, sg = c & 7;
            const uint32_t d = base + 2 * KPL + r * VSTRB + sg * 16;
            const size_t src = ((size_t)kvh * HDn + r) * Tn + t0 + sg * 8;
            cpa16(d, vthp + src);
            cpa16(d + VPL, vtlp + src);
        }
    };
    load_kv(0); cp_commit();

    float O[16][4];
#pragma unroll
    for (int i = 0; i < 16; i++)
#pragma unroll
        for (int e = 0; e < 4; e++) O[i][e] = 0.f;
    float m1 = -1e30f, m2 = -1e30f, l1 = 0.f, l2 = 0.f;

    const int qrow1 = row0 + wid * 16 + (lane >> 2);   // row of c0,c1
    const int lim1 = Pn + qrow1;
    const int lim2 = lim1 + 8;

    const uint32_t qbase = smb +
        (wid * 16 + ((lane >> 3) & 1) * 8 + (lane & 7)) * QSTRB + ((lane >> 4) & 1) * 16;
    const uint32_t brow = ((lane >> 4) & 1) * 8 + (lane & 7);
    const uint32_t bcol = ((lane >> 3) & 1) * 16;

    for (int kt = 0; kt < nkt; kt++) {
        if (kt + 1 < nkt) { load_kv(kt + 1); cp_commit(); cp_wait1(); }
        else cp_wait0();
        __syncthreads();
        const uint32_t base = smb + FKOFF + (kt & 1) * FSTG;

        // ---- S = Q @ K^T (3-split) ----
        float S[8][4];
#pragma unroll
        for (int nt = 0; nt < 8; nt++)
#pragma unroll
            for (int e = 0; e < 4; e++) S[nt][e] = 0.f;
#pragma unroll
        for (int ks = 0; ks < 8; ks++) {
            uint32_t qa_h[4], qa_l[4];
            ldm4(qa_h, qbase + ks * 32);
            ldm4(qa_l, qbase + ks * 32 + QPL);
#pragma unroll
            for (int p = 0; p < 4; p++) {
                uint32_t rh[4], rl[4];
                const uint32_t a = base + (p * 16 + brow) * QSTRB + ks * 32 + bcol;
                ldm4(rh, a);
                ldm4(rl, a + KPL);
                uint32_t bh0[2] = {rh[0], rh[1]}, bh1[2] = {rh[2], rh[3]};
                uint32_t bl0[2] = {rl[0], rl[1]}, bl1[2] = {rl[2], rl[3]};
                mma16816(S[2*p],   qa_h, bh0); mma16816(S[2*p],   qa_h, bl0); mma16816(S[2*p],   qa_l, bh0);
                mma16816(S[2*p+1], qa_h, bh1); mma16816(S[2*p+1], qa_h, bl1); mma16816(S[2*p+1], qa_l, bh1);
            }
        }

        // ---- mask + scale + online softmax ----
        const int t0 = kt * TkF;
        float mx1 = -1e30f, mx2 = -1e30f;
#pragma unroll
        for (int nt = 0; nt < 8; nt++) {
            const int tb = t0 + nt * 8 + (lane & 3) * 2;
#pragma unroll
            for (int e = 0; e < 2; e++) {
                S[nt][e]     = (tb + e <= lim1) ? S[nt][e]     * SCALEn : -1e30f;
                S[nt][2 + e] = (tb + e <= lim2) ? S[nt][2 + e] * SCALEn : -1e30f;
                mx1 = fmaxf(mx1, S[nt][e]);
                mx2 = fmaxf(mx2, S[nt][2 + e]);
            }
        }
        mx1 = fmaxf(mx1, __shfl_xor_sync(~0u, mx1, 1));
        mx1 = fmaxf(mx1, __shfl_xor_sync(~0u, mx1, 2));
        mx2 = fmaxf(mx2, __shfl_xor_sync(~0u, mx2, 1));
        mx2 = fmaxf(mx2, __shfl_xor_sync(~0u, mx2, 2));
        const float mn1 = fmaxf(m1, mx1), mn2 = fmaxf(m2, mx2);
        const float sc1 = __expf(fmaxf(m1 - mn1, -80.f));
        const float sc2 = __expf(fmaxf(m2 - mn2, -80.f));
        m1 = mn1; m2 = mn2;
        float rs1 = 0.f, rs2 = 0.f;
#pragma unroll
        for (int nt = 0; nt < 8; nt++) {
            S[nt][0] = __expf(fmaxf(S[nt][0] - mn1, -80.f));
            S[nt][1] = __expf(fmaxf(S[nt][1] - mn1, -80.f));
            S[nt][2] = __expf(fmaxf(S[nt][2] - mn2, -80.f));
            S[nt][3] = __expf(fmaxf(S[nt][3] - mn2, -80.f));
            rs1 += S[nt][0] + S[nt][1];
            rs2 += S[nt][2] + S[nt][3];
        }
        rs1 += __shfl_xor_sync(~0u, rs1, 1); rs1 += __shfl_xor_sync(~0u, rs1, 2);
        rs2 += __shfl_xor_sync(~0u, rs2, 1); rs2 += __shfl_xor_sync(~0u, rs2, 2);
        l1 = l1 * sc1 + rs1;
        l2 = l2 * sc2 + rs2;
#pragma unroll
        for (int i = 0; i < 16; i++) {
            O[i][0] *= sc1; O[i][1] *= sc1; O[i][2] *= sc2; O[i][3] *= sc2;
        }

        // ---- O += P @ V (3-split; P frags built from S accumulator layout) ----
#pragma unroll
        for (int ks2 = 0; ks2 < 4; ks2++) {
            uint32_t pa_h[4], pa_l[4];
#pragma unroll
            for (int half = 0; half < 2; half++) {
                const int nt = 2 * ks2 + half;
                bf16 h0, g0, h1, g1, h2, g2, h3, g3;
                split_bf16(S[nt][0], h0, g0); split_bf16(S[nt][1], h1, g1);
                split_bf16(S[nt][2], h2, g2); split_bf16(S[nt][3], h3, g3);
                pa_h[half ? 2 : 0] = b2u(__nv_bfloat162(h0, h1));   // a0 / a2: row r1
                pa_h[half ? 3 : 1] = b2u(__nv_bfloat162(h2, h3));   // a1 / a3: row r2
                pa_l[half ? 2 : 0] = b2u(__nv_bfloat162(g0, g1));
                pa_l[half ? 3 : 1] = b2u(__nv_bfloat162(g2, g3));
            }
#pragma unroll
            for (int p2 = 0; p2 < 8; p2++) {
                uint32_t rv[4], rvl[4];
                const uint32_t a = base + 2 * KPL + (p2 * 16 + brow) * VSTRB + ks2 * 32 + bcol;
                ldm4(rv, a);
                ldm4(rvl, a + VPL);
                uint32_t b0[2] = {rv[0], rv[1]},  b1[2] = {rv[2], rv[3]};
                uint32_t c0[2] = {rvl[0], rvl[1]}, c1[2] = {rvl[2], rvl[3]};
                mma16816(O[2*p2],   pa_h, b0); mma16816(O[2*p2],   pa_h, c0); mma16816(O[2*p2],   pa_l, b0);
                mma16816(O[2*p2+1], pa_h, b1); mma16816(O[2*p2+1], pa_h, c1); mma16816(O[2*p2+1], pa_l, b1);
            }
        }
        __syncthreads();
    }

    // ---- epilogue: O /= l, write bf16 hi/lo ----
    const float inv1 = 1.f / l1, inv2 = 1.f / l2;
    const int r1 = qrow1, r2 = qrow1 + 8;
    const int colb = h * HDn + (lane & 3) * 2;
#pragma unroll
    for (int nt2 = 0; nt2 < 16; nt2++) {
        const int col = colb + nt2 * 8;
        bf16 a0, b0, a1, b1;
        split_bf16(O[nt2][0] * inv1, a0, b0);
        split_bf16(O[nt2][1] * inv1, a1, b1);
        *reinterpret_cast<uint32_t*>(ohp + (size_t)r1 * Hn + col) = b2u(__nv_bfloat162(a0, a1));
        *reinterpret_cast<uint32_t*>(olp + (size_t)r1 * Hn + col) = b2u(__nv_bfloat162(b0, b1));
        split_bf16(O[nt2][2] * inv2, a0, b0);
        split_bf16(O[nt2][3] * inv2, a1, b1);
        *reinterpret_cast<uint32_t*>(ohp + (size_t)r2 * Hn + col) = b2u(__nv_bfloat162(a0, a1));
        *reinterpret_cast<uint32_t*>(olp + (size_t)r2 * Hn + col) = b2u(__nv_bfloat162(b0, b1));
    }
}

// ---------------- weight transpose + split (vectorized): in[K,N] fp32 -> out[N,K] bf16 hi/lo ----
struct __align__(16) B8 { bf16 v[8]; };

__global__ void __launch_bounds__(256)
convT_kernel(const float* __restrict__ in, bf16* __restrict__ hi, bf16* __restrict__ lo,
             int K, int N)
{
    __shared__ float s[32][129];
    const int n0 = blockIdx.x * 128, k0 = blockIdx.y * 32;
    const int t = threadIdx.x;
    const int r = t >> 5, c4 = (t & 31) * 4;
#pragma unroll
    for (int rr = 0; rr < 4; rr++) {
        const int k = r + rr * 8;
        float4 v = *reinterpret_cast<const float4*>(in + (size_t)(k0 + k) * N + n0 + c4);
        s[k][c4] = v.x; s[k][c4+1] = v.y; s[k][c4+2] = v.z; s[k][c4+3] = v.w;
    }
    __syncthreads();
    const int n = t >> 1, kk0 = (t & 1) * 16;
    B8 hb[2], lb[2];
#pragma unroll
    for (int kk = 0; kk < 16; kk++) {
        bf16 h, l;
        split_bf16(s[kk0 + kk][n], h, l);
        hb[kk >> 3].v[kk & 7] = h;
        lb[kk >> 3].v[kk & 7] = l;
    }
    const size_t o = (size_t)(n0 + n) * K + k0 + kk0;
    *reinterpret_cast<B8*>(hi + o)     = hb[0];
    *reinterpret_cast<B8*>(hi + o + 8) = hb[1];
    *reinterpret_cast<B8*>(lo + o)     = lb[0];
    *reinterpret_cast<B8*>(lo + o + 8) = lb[1];
}

// ---------------- pack QKV biases into one 2560-vector ----------------
__global__ void packbias_kernel(const float* __restrict__ bq, const float* __restrict__ bk,
                                const float* __restrict__ bv, float* __restrict__ o)
{
    int i = blockIdx.x * 256 + threadIdx.x;
    if (i < 2048) o[i] = bq[i];
    else if (i < 2304) o[i] = bk[i - 2048];
    else if (i < 2560) o[i] = bv[i - 2304];
}

// ---------------- RMSNorm: MODE 0 -> fp32 out, MODE 1 -> bf16 hi/lo ----------------
template<int MODE>
__global__ void __launch_bounds__(256)
rmsnorm_kernel(const float* __restrict__ x, const float* __restrict__ w,
               float* __restrict__ yf, bf16* __restrict__ yh, bf16* __restrict__ yl)
{
    int s = blockIdx.x;
    const float* row = x + (size_t)s * Hn;
    float4 buf[2];
    float ss = 0.f;
#pragma unroll
    for (int it = 0; it < 2; it++) {
        int j = (it * 256 + threadIdx.x) * 4;
        float4 v = *reinterpret_cast<const float4*>(row + j);
        buf[it] = v;
        ss += v.x * v.x + v.y * v.y + v.z * v.z + v.w * v.w;
    }
    ss = blockSum256(ss);
    float inv = rsqrtf(ss * (1.0f / Hn) + EPSn);
#pragma unroll
    for (int it = 0; it < 2; it++) {
        int j = (it * 256 + threadIdx.x) * 4;
        float4 wv = *reinterpret_cast<const float4*>(w + j);
        float o0 = buf[it].x * inv * wv.x;
        float o1 = buf[it].y * inv * wv.y;
        float o2 = buf[it].z * inv * wv.z;
        float o3 = buf[it].w * inv * wv.w;
        if (MODE == 0) {
            *reinterpret_cast<float4*>(yf + (size_t)s * Hn + j) = make_float4(o0, o1, o2, o3);
        } else {
            bf16 h0,l0,h1,l1,h2,l2,h3,l3;
            split_bf16(o0,h0,l0); split_bf16(o1,h1,l1);
            split_bf16(o2,h2,l2); split_bf16(o3,h3,l3);
            __nv_bfloat162 hh0(h0,h1), hh1(h2,h3), ll0(l0,l1), ll1(l2,l3);
            uint2 uh = make_uint2(b2u(hh0), b2u(hh1));
            uint2 ul = make_uint2(b2u(ll0), b2u(ll1));
            *reinterpret_cast<uint2*>(yh + (size_t)s * Hn + j) = uh;
            *reinterpret_cast<uint2*>(yl + (size_t)s * Hn + j) = ul;
        }
    }
}

// ---------------- RoPE for Q: fp32 (strided in qkv) -> bf16 hi/lo dense [S,2048] ----------------
__global__ void rope_q_kernel(const float* __restrict__ qkv, const int* __restrict__ pos,
                              bf16* __restrict__ qh, bf16* __restrict__ ql)
{
    int s = blockIdx.x, h = blockIdx.y, d = threadIdx.x; // d in [0,64)
    double ang = (double)pos[s] * exp(-(double)d / 64.0 * 13.815510557964274);
    double sd, cd; sincos(ang, &sd, &cd);
    float c = (float)cd, sn = (float)sd;
    size_t ibase = (size_t)s * 2560 + h * HDn;
    size_t obase = ((size_t)s * NHn + h) * HDn;
    float x1 = qkv[ibase + d], x2 = qkv[ibase + d + 64];
    float v1 = x1 * c - x2 * sn;
    float v2 = x2 * c + x1 * sn;
    bf16 hh, ll;
    split_bf16(v1, hh, ll); qh[obase + d] = hh;      ql[obase + d] = ll;
    split_bf16(v2, hh, ll); qh[obase + d + 64] = hh; ql[obase + d + 64] = ll;
}

// ---------------- K/V cache: fp32 caches (to d_out) + bf16 hi/lo K + transposed V ----------------
__global__ void kv_cache_kernel(const float* __restrict__ qkv,
                                const float* __restrict__ pastk, const float* __restrict__ pastv,
                                const int* __restrict__ pos,
                                float* __restrict__ kc, float* __restrict__ vc,
                                bf16* __restrict__ kh, bf16* __restrict__ kl,
                                bf16* __restrict__ vth, bf16* __restrict__ vtl)
{
    int t = blockIdx.x, kv = blockIdx.y, d = threadIdx.x; // d in [0,128)
    size_t oidx = ((size_t)kv * Tn + t) * HDn + d;
    float kval, vval;
    if (t < Pn) {
        size_t pidx = ((size_t)kv * Pn + t) * HDn + d;
        kval = pastk[pidx];
        vval = pastv[pidx];
    } else {
        int s = t - Pn;
        const float* kr = qkv + (size_t)s * 2560 + 2048 + kv * HDn;
        int dr = d & 63;
        double ang = (double)pos[s] * exp(-(double)dr / 64.0 * 13.815510557964274);
        double sd, cd; sincos(ang, &sd, &cd);
        float c = (float)cd, sn = (float)sd;
        if (d < 64) kval = kr[d] * c - kr[d + 64] * sn;
        else        kval = kr[d] * c + kr[d - 64] * sn;
        vval = qkv[(size_t)s * 2560 + 2304 + kv * HDn + d];
    }
    kc[oidx] = kval;
    vc[oidx] = vval;
    bf16 h, l;
    split_bf16(kval, h, l); kh[oidx] = h; kl[oidx] = l;
    split_bf16(vval, h, l);
    size_t tidx = ((size_t)kv * HDn + d) * Tn + t;
    vth[tidx] = h; vtl[tidx] = l;
}

// ---------------- SiLU(gate) * up -> bf16 hi/lo (reads fused [S,11264] buffer) ----------------
__global__ void silu_mul_kernel(const float* __restrict__ gu,
                                bf16* __restrict__ oh, bf16* __restrict__ ol, int n4)
{
    int i = blockIdx.x * blockDim.x + threadIdx.x;
    if (i < n4) {
        const int m = i / (FFn / 4);
        const int j = (i - m * (FFn / 4)) * 4;
        const size_t gbase = (size_t)m * (2 * FFn);
        float4 gv = *reinterpret_cast<const float4*>(gu + gbase + j);
        float4 uv = *reinterpret_cast<const float4*>(gu + gbase + FFn + j);
        float r0 = gv.x / (1.f + expf(-gv.x)) * uv.x;
        float r1 = gv.y / (1.f + expf(-gv.y)) * uv.y;
        float r2 = gv.z / (1.f + expf(-gv.z)) * uv.z;
        float r3 = gv.w / (1.f + expf(-gv.w)) * uv.w;
        bf16 h0,l0,h1,l1,h2,l2,h3,l3;
        split_bf16(r0,h0,l0); split_bf16(r1,h1,l1);
        split_bf16(r2,h2,l2); split_bf16(r3,h3,l3);
        __nv_bfloat162 hh0(h0,h1), hh1(h2,h3), ll0(l0,l1), ll1(l2,l3);
        uint2 uh = make_uint2(b2u(hh0), b2u(hh1));
        uint2 ul = make_uint2(b2u(ll0), b2u(ll1));
        *reinterpret_cast<uint2*>(oh + (size_t)m * FFn + j) = uh;
        *reinterpret_cast<uint2*>(ol + (size_t)m * FFn + j) = ul;
    }
}

// ---------------- host-side launch helper ----------------
static void mmagemm(const bf16* Ah, const bf16* Al, const bf16* Bh, const bf16* Bl,
                    const float* bias, const float* Res, float* Cf,
                    int M, int N, int K, int lda, int ldb, int ldc)
{
    dim3 grid(N / 128, M / 128, 1);
    mma_gemm<<<grid, 256, NSTAGE * STAGEB>>>(Ah, Al, Bh, Bl, bias, Res, Cf, K, lda, ldb, ldc);
}

extern "C" void kernel_launch(void* const* d_in, const int* in_sizes, int n_in,
                              void* d_out, int out_size)
{
    (void)in_sizes; (void)n_in; (void)out_size;
    const float* embeds = (const float*)d_in[0];
    const int*   pos    = (const int*)  d_in[1];
    const float* past_k = (const float*)d_in[2];
    const float* past_v = (const float*)d_in[3];
    const float* ln1    = (const float*)d_in[4];
    const float* wq     = (const float*)d_in[5];
    const float* bq     = (const float*)d_in[6];
    const float* wk     = (const float*)d_in[7];
    const float* bk     = (const float*)d_in[8];
    const float* wv     = (const float*)d_in[9];
    const float* bv     = (const float*)d_in[10];
    const float* wo     = (const float*)d_in[11];
    const float* ln2    = (const float*)d_in[12];
    const float* wg     = (const float*)d_in[13];
    const float* wu     = (const float*)d_in[14];
    const float* wd     = (const float*)d_in[15];
    const float* normw  = (const float*)d_in[16];
    float* out = (float*)d_out;

    cudaFuncSetAttribute(mma_gemm, cudaFuncAttributeMaxDynamicSharedMemorySize, NSTAGE * STAGEB);
    cudaFuncSetAttribute(flash_kernel, cudaFuncAttributeMaxDynamicSharedMemorySize, FSMEM);

    float *hid, *qkv, *gu, *bqkv;
    cudaGetSymbolAddress((void**)&hid,  g_hid);
    cudaGetSymbolAddress((void**)&qkv,  g_qkv);
    cudaGetSymbolAddress((void**)&gu,   g_gateup);
    cudaGetSymbolAddress((void**)&bqkv, g_bqkv);
    bf16 *hnh,*hnl,*qh,*ql,*kh,*kl,*vth,*vtl,*ath,*atl,*gh,*gl,*wh,*wl;
    cudaGetSymbolAddress((void**)&hnh, g_hn_hi); cudaGetSymbolAddress((void**)&hnl, g_hn_lo);
    cudaGetSymbolAddress((void**)&qh,  g_q_hi);  cudaGetSymbolAddress((void**)&ql,  g_q_lo);
    cudaGetSymbolAddress((void**)&kh,  g_k_hi);  cudaGetSymbolAddress((void**)&kl,  g_k_lo);
    cudaGetSymbolAddress((void**)&vth, g_vt_hi); cudaGetSymbolAddress((void**)&vtl, g_vt_lo);
    cudaGetSymbolAddress((void**)&ath, g_at_hi); cudaGetSymbolAddress((void**)&atl, g_at_lo);
    cudaGetSymbolAddress((void**)&gh,  g_g_hi);  cudaGetSymbolAddress((void**)&gl,  g_g_lo);
    cudaGetSymbolAddress((void**)&wh,  g_w_hi);  cudaGetSymbolAddress((void**)&wl,  g_w_lo);

    // per-layer offsets into transposed weight store (QKV and G|U are contiguous)
    const long long OQ = 0, OO = 5242880, OG = 9437184, OD = 32505856;
    const long long OK_ = 4194304, OV = 4718592, OU = 20971520;

    // ---- transpose + split all weights (vectorized) ----
    dim3 cb(256);
    for (int l = 0; l < Ln; l++) {
        long long base = (long long)l * WL;
        convT_kernel<<<dim3(2048/128, 2048/32), cb>>>(wq + (size_t)l*Hn*2048, wh + base + OQ,  wl + base + OQ,  Hn, 2048);
        convT_kernel<<<dim3(256/128,  2048/32), cb>>>(wk + (size_t)l*Hn*256,  wh + base + OK_, wl + base + OK_, Hn, 256);
        convT_kernel<<<dim3(256/128,  2048/32), cb>>>(wv + (size_t)l*Hn*256,  wh + base + OV,  wl + base + OV,  Hn, 256);
        convT_kernel<<<dim3(2048/128, 2048/32), cb>>>(wo + (size_t)l*Hn*Hn,   wh + base + OO,  wl + base + OO,  Hn, 2048);
        convT_kernel<<<dim3(5632/128, 2048/32), cb>>>(wg + (size_t)l*Hn*FFn,  wh + base + OG,  wl + base + OG,  Hn, FFn);
        convT_kernel<<<dim3(5632/128, 2048/32), cb>>>(wu + (size_t)l*Hn*FFn,  wh + base + OU,  wl + base + OU,  Hn, FFn);
        convT_kernel<<<dim3(2048/128, 5632/32), cb>>>(wd + (size_t)l*FFn*Hn,  wh + base + OD,  wl + base + OD,  FFn, 2048);
    }

    cudaMemcpyAsync(hid, embeds, sizeof(float) * Sn * Hn, cudaMemcpyDeviceToDevice);

    for (int l = 0; l < Ln; l++) {
        long long base = (long long)l * WL;
        float* kc = out + (size_t)Sn * Hn + (size_t)l * 2 * NKVn * Tn * HDn;
        float* vc = kc + (size_t)NKVn * Tn * HDn;

        // pre-attention norm -> bf16 hi/lo
        rmsnorm_kernel<1><<<Sn, 256>>>(hid, ln1 + (size_t)l * Hn, nullptr, hnh, hnl);

        // fused QKV projection (N=2560) -> fp32 qkv buffer
        packbias_kernel<<<10, 256>>>(bq + (size_t)l*2048, bk + (size_t)l*256, bv + (size_t)l*256, bqkv);
        mmagemm(hnh, hnl, wh + base + OQ, wl + base + OQ, bqkv, nullptr,
                qkv, Sn, 2560, Hn, Hn, Hn, 2560);

        // RoPE Q -> bf16 hi/lo; KV cache (fp32 to d_out + bf16 hi/lo, V transposed)
        rope_q_kernel<<<dim3(Sn, NHn), 64>>>(qkv, pos, qh, ql);
        kv_cache_kernel<<<dim3(Tn, NKVn), HDn>>>(
            qkv,
            past_k + (size_t)l * NKVn * Pn * HDn,
            past_v + (size_t)l * NKVn * Pn * HDn,
            pos, kc, vc, kh, kl, vth, vtl);

        // fused attention: QK^T -> online softmax -> PV, bf16 hi/lo out
        flash_kernel<<<dim3(Sn / 128, NHn), 256, FSMEM>>>(qh, ql, kh, kl, vth, vtl, ath, atl);

        // output projection + residual (fp32)
        mmagemm(ath, atl, wh + base + OO, wl + base + OO, nullptr, hid,
                hid, Sn, Hn, Hn, Hn, Hn, Hn);

        // MLP: fused gate|up GEMM (N=11264) -> silu*mul -> down
        rmsnorm_kernel<1><<<Sn, 256>>>(hid, ln2 + (size_t)l * Hn, nullptr, hnh, hnl);
        mmagemm(hnh, hnl, wh + base + OG, wl + base + OG, nullptr, nullptr,
                gu, Sn, 2*FFn, Hn, Hn, Hn, 2*FFn);
        silu_mul_kernel<<<(Sn * FFn / 4 + 255) / 256, 256>>>(gu, gh, gl, Sn * FFn / 4);
        mmagemm(gh, gl, wh + base + OD, wl + base + OD, nullptr, hid,
                hid, Sn, Hn, FFn, FFn, FFn, Hn);
    }

    // final norm -> fp32 hidden output
    rmsnorm_kernel<0><<<Sn, 256>>>(hid, normw, out, nullptr, nullptr);
}